// round 3
// baseline (speedup 1.0000x reference)
#include <cuda_runtime.h>
#include <math.h>

#define NTOK 4096
#define DMODEL 256
#define QSCALE 0.2550760660737454f   /* (1/sqrt(32)) * log2(e) */
#define NEGL2  -1e30f

// Scratch (allocation-free rule: __device__ globals)
static __device__ float g_q[NTOK * DMODEL];
static __device__ float g_k[NTOK * DMODEL];
static __device__ float g_v[NTOK * DMODEL];
static __device__ float g_att[NTOK * DMODEL];

// ---------------- packed f32x2 helpers ----------------
#define FMA2(d, a, b) \
    asm("fma.rn.f32x2 %0, %1, %2, %3;" : "=l"(d) : "l"(a), "l"(b), "l"(d))
#define MUL2(d, a, b) \
    asm("mul.rn.f32x2 %0, %1, %2;" : "=l"(d) : "l"(a), "l"(b))
#define PACK2(d, lo, hi) \
    asm("mov.b64 %0, {%1, %2};" : "=l"(d) : "f"(lo), "f"(hi))

__device__ __forceinline__ float f2_lo(unsigned long long x) {
    return __uint_as_float((unsigned)x);
}
__device__ __forceinline__ float f2_hi(unsigned long long x) {
    return __uint_as_float((unsigned)(x >> 32));
}
__device__ __forceinline__ float ex2(float x) {
    float r;
    asm("ex2.approx.ftz.f32 %0, %1;" : "=f"(r) : "f"(x));
    return r;
}

// ---------------- cp.async helpers ----------------
__device__ __forceinline__ void cp16(float* dst, const float* src) {
    unsigned ds = (unsigned)__cvta_generic_to_shared(dst);
    asm volatile("cp.async.cg.shared.global [%0], [%1], 16;\n" :: "r"(ds), "l"(src));
}
#define CP_COMMIT asm volatile("cp.async.commit_group;\n")
#define CP_WAIT1  asm volatile("cp.async.wait_group 1;\n")
#define CP_WAIT0  asm volatile("cp.async.wait_group 0;\n")

// ---------------------------------------------------------------------------
// C[M,256] = A[M,256] @ W[256,256] + bias   (M = 4096)
// ---------------------------------------------------------------------------
__global__ __launch_bounds__(256) void gemm_bias_kernel(
    const float* __restrict__ A, const float* __restrict__ W,
    const float* __restrict__ bias, float* __restrict__ C)
{
    __shared__ float As[16][68];
    __shared__ float Bs[16][68];

    const int tid = threadIdx.x;
    const int tx = tid & 15;
    const int ty = tid >> 4;
    const int mb = blockIdx.x * 64;
    const int nb = blockIdx.y * 64;

    const int arow = tid >> 2;
    const int ac4  = (tid & 3) << 2;
    const int brow = tid >> 4;
    const int bc4  = (tid & 15) << 2;

    float acc[4][4];
#pragma unroll
    for (int i = 0; i < 4; i++)
#pragma unroll
        for (int j = 0; j < 4; j++) acc[i][j] = 0.f;

    for (int kb = 0; kb < 256; kb += 16) {
        float4 av = *(const float4*)&A[(mb + arow) * 256 + kb + ac4];
        float4 wv = *(const float4*)&W[(kb + brow) * 256 + nb + bc4];
        __syncthreads();
        As[ac4 + 0][arow] = av.x;
        As[ac4 + 1][arow] = av.y;
        As[ac4 + 2][arow] = av.z;
        As[ac4 + 3][arow] = av.w;
        *(float4*)&Bs[brow][bc4] = wv;
        __syncthreads();
#pragma unroll
        for (int kk = 0; kk < 16; kk++) {
            float4 a = *(float4*)&As[kk][ty << 2];
            float4 b = *(float4*)&Bs[kk][tx << 2];
            float a4[4] = {a.x, a.y, a.z, a.w};
            float b4[4] = {b.x, b.y, b.z, b.w};
#pragma unroll
            for (int i = 0; i < 4; i++)
#pragma unroll
                for (int j = 0; j < 4; j++)
                    acc[i][j] += a4[i] * b4[j];
        }
    }

    float4 bv = *(const float4*)&bias[nb + (tx << 2)];
#pragma unroll
    for (int i = 0; i < 4; i++) {
        float4 o;
        o.x = acc[i][0] + bv.x;
        o.y = acc[i][1] + bv.y;
        o.z = acc[i][2] + bv.z;
        o.w = acc[i][3] + bv.w;
        *(float4*)&C[(mb + (ty << 2) + i) * 256 + nb + (tx << 2)] = o;
    }
}

// ---------------------------------------------------------------------------
// Flash attention: block = 32 queries x 8 heads = 256 threads (1 q-head each).
// q lives in registers (packed f32x2, pre-scaled by 1/sqrt(32)*log2e).
// k/v/adj double-buffered via cp.async. Per-head chunk rotation ((c+h)&7)
// keeps all warp-wide LDS.128 conflict-free. Softmax in log2 domain (ex2).
// ---------------------------------------------------------------------------
// smem layout (floats):
//   k buffers: [0, 8192), [8192, 16384)
//   v buffers: [16384, 24576), [24576, 32768)
//   adj buffers (stride 40): [32768, 34048), [34048, 35328)
#define SM_FLOATS 35328

__device__ __forceinline__ void issue_tile(
    int kb, float* ks, float* vs, float* as_,
    const float* gk, const float* gv, const float* __restrict__ adj,
    int qb, int tid)
{
#pragma unroll
    for (int i = 0; i < 8; i++) {
        int idx = tid + (i << 8);      // 0..2047
        int r = idx >> 6;
        int ch = idx & 63;
        int hh = ch >> 3;
        int cc = ch & 7;
        int dst = r * 256 + (hh << 5) + (((cc + hh) & 7) << 2);
        int src = (kb + r) * 256 + (ch << 2);
        cp16(ks + dst, gk + src);
        cp16(vs + dst, gv + src);
    }
    {
        int r = tid >> 3;
        int c4 = (tid & 7) << 2;
        cp16(as_ + r * 40 + c4, adj + (qb + r) * NTOK + kb + c4);
    }
}

__global__ __launch_bounds__(256) void attn_kernel(const float* __restrict__ adj)
{
    extern __shared__ float sm[];
    float* kbuf[2] = { sm,          sm + 8192 };
    float* vbuf[2] = { sm + 16384,  sm + 24576 };
    float* abuf[2] = { sm + 32768,  sm + 34048 };

    const int tid = threadIdx.x;
    const int h = tid & 7;
    const int q = tid >> 3;            // 0..31
    const int qb = blockIdx.x * 32;
    const int hb = h << 5;

    // load + scale + pack q (registers only)
    unsigned long long qpk[16];
    {
        const float* qrow = g_q + (qb + q) * 256 + hb;
#pragma unroll
        for (int c = 0; c < 8; c++) {
            float4 t = *(const float4*)(qrow + (c << 2));
            PACK2(qpk[2 * c],     t.x * QSCALE, t.y * QSCALE);
            PACK2(qpk[2 * c + 1], t.z * QSCALE, t.w * QSCALE);
        }
    }

    unsigned long long acc2[16];
#pragma unroll
    for (int i = 0; i < 16; i++) acc2[i] = 0ull;
    float m = NEGL2, l = 0.f;

    issue_tile(0, kbuf[0], vbuf[0], abuf[0], g_k, g_v, adj, qb, tid);
    CP_COMMIT;

    for (int t = 0; t < 128; t++) {
        const int cur = t & 1;
        if (t < 127) {
            issue_tile((t + 1) << 5, kbuf[cur ^ 1], vbuf[cur ^ 1], abuf[cur ^ 1],
                       g_k, g_v, adj, qb, tid);
            CP_COMMIT;
            CP_WAIT1;
        } else {
            CP_WAIT0;
        }
        __syncthreads();

        const float* ks = kbuf[cur];
        const float* vs = vbuf[cur];
        const float* as_ = abuf[cur];

        // ----- scores (packed pairwise dims) -----
        unsigned long long s2[32];
#pragma unroll
        for (int j = 0; j < 32; j++) s2[j] = 0ull;
#pragma unroll
        for (int c = 0; c < 8; c++) {
            const int off = hb + (((c + h) & 7) << 2);
            unsigned long long qa = qpk[2 * c];
            unsigned long long qc = qpk[2 * c + 1];
#pragma unroll
            for (int j = 0; j < 32; j++) {
                ulonglong2 kv = *(const ulonglong2*)(ks + j * 256 + off);
                FMA2(s2[j], qa, kv.x);
                FMA2(s2[j], qc, kv.y);
            }
        }

        // ----- reduce pairs, mask, online softmax (log2 domain) -----
        float s[32];
        float mx = m;
#pragma unroll
        for (int j = 0; j < 32; j++) {
            float sv = f2_lo(s2[j]) + f2_hi(s2[j]);
            float e = as_[q * 40 + j];
            sv = (e > 0.f) ? sv : NEGL2;
            s[j] = sv;
            mx = fmaxf(mx, sv);
        }
        float corr = ex2(m - mx);
        m = mx;
        float ps = 0.f;
#pragma unroll
        for (int j = 0; j < 32; j++) {
            s[j] = ex2(s[j] - mx);
            ps += s[j];
        }
        l = l * corr + ps;
        {
            unsigned long long cd;
            PACK2(cd, corr, corr);
#pragma unroll
            for (int i = 0; i < 16; i++) MUL2(acc2[i], acc2[i], cd);
        }

        // ----- AV accumulate (packed) -----
#pragma unroll
        for (int j = 0; j < 32; j++) {
            unsigned long long pd;
            PACK2(pd, s[j], s[j]);
            const float* vr = vs + j * 256 + hb;
#pragma unroll
            for (int c = 0; c < 8; c++) {
                const int ro = ((c + h) & 7) << 2;
                ulonglong2 vv = *(const ulonglong2*)(vr + ro);
                FMA2(acc2[2 * c],     pd, vv.x);
                FMA2(acc2[2 * c + 1], pd, vv.y);
            }
        }

        __syncthreads();
    }

    // ----- epilogue -----
    float inv = 1.f / l;
    float* orow = g_att + (qb + q) * 256 + hb;
#pragma unroll
    for (int c = 0; c < 8; c++) {
        float4 o;
        o.x = f2_lo(acc2[2 * c]) * inv;
        o.y = f2_hi(acc2[2 * c]) * inv;
        o.z = f2_lo(acc2[2 * c + 1]) * inv;
        o.w = f2_hi(acc2[2 * c + 1]) * inv;
        *(float4*)(orow + (c << 2)) = o;
    }
}

// ---------------------------------------------------------------------------
extern "C" void kernel_launch(void* const* d_in, const int* in_sizes, int n_in,
                              void* d_out, int out_size)
{
    (void)in_sizes; (void)n_in; (void)out_size;
    const float* x   = (const float*)d_in[0];
    const float* adj = (const float*)d_in[1];
    const float* Wq  = (const float*)d_in[2];
    const float* bq  = (const float*)d_in[3];
    const float* Wk  = (const float*)d_in[4];
    const float* bk  = (const float*)d_in[5];
    const float* Wv  = (const float*)d_in[6];
    const float* bv  = (const float*)d_in[7];
    const float* Wo  = (const float*)d_in[8];
    const float* bo  = (const float*)d_in[9];
    float* out = (float*)d_out;

    float *pq, *pk, *pv, *pa;
    cudaGetSymbolAddress((void**)&pq, g_q);
    cudaGetSymbolAddress((void**)&pk, g_k);
    cudaGetSymbolAddress((void**)&pv, g_v);
    cudaGetSymbolAddress((void**)&pa, g_att);

    const int attn_smem = SM_FLOATS * 4;   // 141312 B
    cudaFuncSetAttribute(attn_kernel,
                         cudaFuncAttributeMaxDynamicSharedMemorySize, attn_smem);

    dim3 gg(64, 4);
    gemm_bias_kernel<<<gg, 256>>>(x, Wq, bq, pq);
    gemm_bias_kernel<<<gg, 256>>>(x, Wk, bk, pk);
    gemm_bias_kernel<<<gg, 256>>>(x, Wv, bv, pv);
    attn_kernel<<<128, 256, attn_smem>>>(adj);
    gemm_bias_kernel<<<gg, 256>>>(pa, Wo, bo, out);
}

// round 4
// speedup vs baseline: 4.4053x; 4.4053x over previous
#include <cuda_runtime.h>
#include <cuda_bf16.h>
#include <math.h>

#define NTOK 4096
#define QSCALE 0.2550760660737454f   /* (1/sqrt(32)) * log2(e) */
#define NEGL2  -1e30f

// ---- device scratch (allocation-free rule). bf16 arrays are stored in
// tile-swizzled layout: tile = row>>5 (16KB blocks), within tile the 16B
// chunk index is (col>>3) ^ (row&7)  -> conflict-free ldmatrix after a raw
// 1D bulk copy into smem.
static __device__ __align__(1024) float g_att[NTOK * 256];
static __device__ __align__(1024) __nv_bfloat16 g_qh[NTOK * 256], g_ql[NTOK * 256];
static __device__ __align__(1024) __nv_bfloat16 g_kh[NTOK * 256], g_kl[NTOK * 256];
static __device__ __align__(1024) __nv_bfloat16 g_vh[NTOK * 256], g_vl[NTOK * 256];
static __device__ __align__(1024) unsigned g_amask[128 * NTOK];   // [tile][q]

// ---------------- helpers ----------------
__device__ __forceinline__ float ex2(float x) {
    float r;
    asm("ex2.approx.ftz.f32 %0, %1;" : "=f"(r) : "f"(x));
    return r;
}
// d = bf16x2{hi, lo}
#define PKBF(d, lo, hi) \
    asm("cvt.rn.bf16x2.f32 %0, %1, %2;" : "=r"(d) : "f"(hi), "f"(lo))

__device__ __forceinline__ void ldsm4(uint4& r, unsigned addr) {
    asm volatile("ldmatrix.sync.aligned.m8n8.x4.shared.b16 {%0,%1,%2,%3}, [%4];"
                 : "=r"(r.x), "=r"(r.y), "=r"(r.z), "=r"(r.w) : "r"(addr));
}
__device__ __forceinline__ void ldsm4t(uint4& r, unsigned addr) {
    asm volatile("ldmatrix.sync.aligned.m8n8.x4.trans.shared.b16 {%0,%1,%2,%3}, [%4];"
                 : "=r"(r.x), "=r"(r.y), "=r"(r.z), "=r"(r.w) : "r"(addr));
}
__device__ __forceinline__ void mma_bf16(
    float& d0, float& d1, float& d2, float& d3,
    unsigned a0, unsigned a1, unsigned a2, unsigned a3,
    unsigned b0, unsigned b1)
{
    asm("mma.sync.aligned.m16n8k16.row.col.f32.bf16.bf16.f32 "
        "{%0,%1,%2,%3},{%4,%5,%6,%7},{%8,%9},{%0,%1,%2,%3};"
        : "+f"(d0), "+f"(d1), "+f"(d2), "+f"(d3)
        : "r"(a0), "r"(a1), "r"(a2), "r"(a3), "r"(b0), "r"(b1));
}

__device__ __forceinline__ void mbar_init(unsigned addr, unsigned cnt) {
    asm volatile("mbarrier.init.shared.b64 [%0], %1;" :: "r"(addr), "r"(cnt) : "memory");
}
__device__ __forceinline__ void mbar_expect(unsigned addr, unsigned tx) {
    asm volatile("mbarrier.arrive.expect_tx.shared.b64 _, [%0], %1;"
                 :: "r"(addr), "r"(tx) : "memory");
}
__device__ __forceinline__ void mbar_wait(unsigned addr, unsigned phase) {
    unsigned done = 0;
    while (!done) {
        asm volatile(
            "{\n .reg .pred p;\n"
            " mbarrier.try_wait.parity.acquire.cta.shared::cta.b64 p, [%1], %2, 0x989680;\n"
            " selp.b32 %0, 1, 0, p;\n}"
            : "=r"(done) : "r"(addr), "r"(phase) : "memory");
    }
}
__device__ __forceinline__ void bulkcp(unsigned dst, const void* src,
                                       unsigned bytes, unsigned mbar) {
    unsigned long long ga;
    asm("cvta.to.global.u64 %0, %1;" : "=l"(ga) : "l"(src));
    asm volatile(
        "cp.async.bulk.shared::cta.global.mbarrier::complete_tx::bytes "
        "[%0], [%1], %2, [%3];"
        :: "r"(dst), "l"(ga), "r"(bytes), "r"(mbar) : "memory");
}

// swizzled byte offset within a 32x512B tile block
__device__ __forceinline__ unsigned swz(int row, int colbf16) {
    return (unsigned)(row * 512 + ((((colbf16 >> 3) ^ (row & 7))) << 4)
                      + ((colbf16 & 7) << 1));
}

// ---------------------------------------------------------------------------
// adj -> bitmask: g_amask[t*4096 + q] bit j = adj[q][t*32+j] > 0
// ---------------------------------------------------------------------------
__global__ __launch_bounds__(256) void mask_kernel(const float* __restrict__ adj)
{
    int wid = (blockIdx.x * blockDim.x + threadIdx.x) >> 5;  // 0..16383
    int lane = threadIdx.x & 31;
    int qb = (wid >> 7) << 5;
    int t = wid & 127;
    const float* base = adj + t * 32 + lane;
    unsigned my = 0;
#pragma unroll 8
    for (int r = 0; r < 32; r++) {
        float v = base[(size_t)(qb + r) * NTOK];
        unsigned w = __ballot_sync(0xffffffffu, v > 0.f);
        if (lane == r) my = w;
    }
    g_amask[t * NTOK + qb + lane] = my;
}

// ---------------------------------------------------------------------------
// GEMM: C = A[M,256] @ W[256,256] + bias.
// MODE 0: fp32 row-major out.  MODE 1: hi/lo bf16 out, tile-swizzled, *scale.
// ---------------------------------------------------------------------------
template <int MODE>
__global__ __launch_bounds__(256) void gemm_bias_kernel(
    const float* __restrict__ A, const float* __restrict__ W,
    const float* __restrict__ bias, float* __restrict__ Cf,
    __nv_bfloat16* __restrict__ Ch, __nv_bfloat16* __restrict__ Cl, float scale)
{
    __shared__ float As[16][68];
    __shared__ float Bs[16][68];

    const int tid = threadIdx.x;
    const int tx = tid & 15;
    const int ty = tid >> 4;
    const int mb = blockIdx.x * 64;
    const int nb = blockIdx.y * 64;

    const int arow = tid >> 2;
    const int ac4  = (tid & 3) << 2;
    const int brow = tid >> 4;
    const int bc4  = (tid & 15) << 2;

    float acc[4][4];
#pragma unroll
    for (int i = 0; i < 4; i++)
#pragma unroll
        for (int j = 0; j < 4; j++) acc[i][j] = 0.f;

    for (int kb = 0; kb < 256; kb += 16) {
        float4 av = *(const float4*)&A[(mb + arow) * 256 + kb + ac4];
        float4 wv = *(const float4*)&W[(kb + brow) * 256 + nb + bc4];
        __syncthreads();
        As[ac4 + 0][arow] = av.x;
        As[ac4 + 1][arow] = av.y;
        As[ac4 + 2][arow] = av.z;
        As[ac4 + 3][arow] = av.w;
        *(float4*)&Bs[brow][bc4] = wv;
        __syncthreads();
#pragma unroll
        for (int kk = 0; kk < 16; kk++) {
            float4 a = *(float4*)&As[kk][ty << 2];
            float4 b = *(float4*)&Bs[kk][tx << 2];
            float a4[4] = {a.x, a.y, a.z, a.w};
            float b4[4] = {b.x, b.y, b.z, b.w};
#pragma unroll
            for (int i = 0; i < 4; i++)
#pragma unroll
                for (int j = 0; j < 4; j++)
                    acc[i][j] += a4[i] * b4[j];
        }
    }

    float4 bv = *(const float4*)&bias[nb + (tx << 2)];
#pragma unroll
    for (int i = 0; i < 4; i++) {
        int row = mb + (ty << 2) + i;
        int col = nb + (tx << 2);
        float v0 = acc[i][0] + bv.x, v1 = acc[i][1] + bv.y;
        float v2 = acc[i][2] + bv.z, v3 = acc[i][3] + bv.w;
        if (MODE == 0) {
            float4 o = {v0, v1, v2, v3};
            *(float4*)&Cf[row * 256 + col] = o;
        } else {
            v0 *= scale; v1 *= scale; v2 *= scale; v3 *= scale;
            unsigned hp0, hp1, lp0, lp1;
            PKBF(hp0, v0, v1);
            PKBF(hp1, v2, v3);
            float r0 = v0 - __uint_as_float(hp0 << 16);
            float r1 = v1 - __uint_as_float(hp0 & 0xffff0000u);
            float r2 = v2 - __uint_as_float(hp1 << 16);
            float r3 = v3 - __uint_as_float(hp1 & 0xffff0000u);
            PKBF(lp0, r0, r1);
            PKBF(lp1, r2, r3);
            unsigned off = ((unsigned)(row >> 5) << 14) + swz(row & 31, col);
            uint2 hw = {hp0, hp1}, lw = {lp0, lp1};
            *(uint2*)((char*)Ch + off) = hw;
            *(uint2*)((char*)Cl + off) = lw;
        }
    }
}

// ---------------------------------------------------------------------------
// Tensor-core flash attention.
// Block = 512 threads / 16 warps: warp w -> head w&7, q-half w>>3.
// 32 queries/block, key tile 32, grid 128, TMA-bulk double buffering.
// ---------------------------------------------------------------------------
#define QH_OFF 0
#define QL_OFF 16384
#define TILE_OFF 32768
#define ARR 16384
#define BUF 65536
#define BAR_OFF 163840
#define SMEM_BYTES 163872

__device__ __forceinline__ void stage_tile(unsigned sb, int t, int buf) {
    unsigned bar = sb + BAR_OFF + buf * 8;
    unsigned base = sb + TILE_OFF + buf * BUF;
    size_t go = (size_t)t << 14;
    mbar_expect(bar, 4 * ARR);
    bulkcp(base,           (const char*)g_kh + go, ARR, bar);
    bulkcp(base + ARR,     (const char*)g_kl + go, ARR, bar);
    bulkcp(base + 2 * ARR, (const char*)g_vh + go, ARR, bar);
    bulkcp(base + 3 * ARR, (const char*)g_vl + go, ARR, bar);
}

__global__ __launch_bounds__(512, 1) void attn_kernel()
{
    extern __shared__ char smc[];
    unsigned sb = (unsigned)__cvta_generic_to_shared(smc);

    const int tid = threadIdx.x;
    const int lane = tid & 31;
    const int w = tid >> 5;
    const int hb = (w & 7) << 5;          // head's bf16 col base
    const int qoff = (w >> 3) << 4;       // 0 or 16
    const int qb = blockIdx.x << 5;
    const int g = lane >> 2, tig = lane & 3;
    const int l7 = lane & 7, lb3 = (lane >> 3) & 1, lb4 = lane >> 4;

    if (tid == 0) {
        mbar_init(sb + BAR_OFF, 1);
        mbar_init(sb + BAR_OFF + 8, 1);
        mbar_init(sb + BAR_OFF + 16, 1);
        asm volatile("fence.proxy.async.shared::cta;" ::: "memory");
    }
    __syncthreads();
    if (tid == 0) {
        unsigned qbar = sb + BAR_OFF + 16;
        size_t go = (size_t)blockIdx.x << 14;
        mbar_expect(qbar, 2 * ARR);
        bulkcp(sb + QH_OFF, (const char*)g_qh + go, ARR, qbar);
        bulkcp(sb + QL_OFF, (const char*)g_ql + go, ARR, qbar);
        stage_tile(sb, 0, 0);
        stage_tile(sb, 1, 1);
    }

    // mask prefetch (tile 0)
    const unsigned* am = g_amask + qb + qoff + g;
    unsigned mw0 = __ldg(am);
    unsigned mw1 = __ldg(am + 8);

    mbar_wait(sb + BAR_OFF + 16, 0);

    // Q fragments, kept in registers for whole kernel
    unsigned qhf[2][4], qlf[2][4];
#pragma unroll
    for (int kc = 0; kc < 2; kc++) {
        unsigned off = swz(qoff + (lane & 15), hb + kc * 16 + ((lane >> 4) << 3));
        uint4 r;
        ldsm4(r, sb + QH_OFF + off);
        qhf[kc][0] = r.x; qhf[kc][1] = r.y; qhf[kc][2] = r.z; qhf[kc][3] = r.w;
        ldsm4(r, sb + QL_OFF + off);
        qlf[kc][0] = r.x; qlf[kc][1] = r.y; qlf[kc][2] = r.z; qlf[kc][3] = r.w;
    }

    float oc[4][4];
#pragma unroll
    for (int i = 0; i < 4; i++)
#pragma unroll
        for (int j = 0; j < 4; j++) oc[i][j] = 0.f;
    float m0 = NEGL2, m1 = NEGL2, l0 = 0.f, l1 = 0.f;

    for (int t = 0; t < 128; t++) {
        unsigned nw0 = 0, nw1 = 0;
        if (t < 127) {
            nw0 = __ldg(am + (t + 1) * NTOK);
            nw1 = __ldg(am + (t + 1) * NTOK + 8);
        }
        const int cur = t & 1;
        mbar_wait(sb + BAR_OFF + cur * 8, (t >> 1) & 1);
        const unsigned tb = sb + TILE_OFF + cur * BUF;

        // ---- K fragments ----
        uint4 khf[2][2], klf[2][2];
#pragma unroll
        for (int kc = 0; kc < 2; kc++)
#pragma unroll
            for (int p = 0; p < 2; p++) {
                unsigned off = swz(16 * p + lb4 * 8 + l7, hb + kc * 16 + lb3 * 8);
                ldsm4(khf[kc][p], tb + off);
                ldsm4(klf[kc][p], tb + ARR + off);
            }

        // ---- S = qh@kh + ql@kh + qh@kl ----
        float sc[4][4];
#pragma unroll
        for (int i = 0; i < 4; i++)
#pragma unroll
            for (int j = 0; j < 4; j++) sc[i][j] = 0.f;
#pragma unroll
        for (int nt = 0; nt < 4; nt++) {
            const int p = nt >> 1, s = nt & 1;
#pragma unroll
            for (int kc = 0; kc < 2; kc++) {
                unsigned bh0 = s ? khf[kc][p].z : khf[kc][p].x;
                unsigned bh1 = s ? khf[kc][p].w : khf[kc][p].y;
                unsigned bl0 = s ? klf[kc][p].z : klf[kc][p].x;
                unsigned bl1 = s ? klf[kc][p].w : klf[kc][p].y;
                mma_bf16(sc[nt][0], sc[nt][1], sc[nt][2], sc[nt][3],
                         qhf[kc][0], qhf[kc][1], qhf[kc][2], qhf[kc][3], bh0, bh1);
                mma_bf16(sc[nt][0], sc[nt][1], sc[nt][2], sc[nt][3],
                         qlf[kc][0], qlf[kc][1], qlf[kc][2], qlf[kc][3], bh0, bh1);
                mma_bf16(sc[nt][0], sc[nt][1], sc[nt][2], sc[nt][3],
                         qhf[kc][0], qhf[kc][1], qhf[kc][2], qhf[kc][3], bl0, bl1);
            }
        }

        // ---- mask + online softmax (log2 domain; q pre-scaled) ----
        float rm0 = NEGL2, rm1 = NEGL2;
#pragma unroll
        for (int nt = 0; nt < 4; nt++) {
            int j0 = nt * 8 + 2 * tig;
            sc[nt][0] = ((mw0 >> j0) & 1) ? sc[nt][0] : NEGL2;
            sc[nt][1] = ((mw0 >> (j0 + 1)) & 1) ? sc[nt][1] : NEGL2;
            sc[nt][2] = ((mw1 >> j0) & 1) ? sc[nt][2] : NEGL2;
            sc[nt][3] = ((mw1 >> (j0 + 1)) & 1) ? sc[nt][3] : NEGL2;
            rm0 = fmaxf(rm0, fmaxf(sc[nt][0], sc[nt][1]));
            rm1 = fmaxf(rm1, fmaxf(sc[nt][2], sc[nt][3]));
        }
        rm0 = fmaxf(rm0, __shfl_xor_sync(0xffffffffu, rm0, 1));
        rm0 = fmaxf(rm0, __shfl_xor_sync(0xffffffffu, rm0, 2));
        rm1 = fmaxf(rm1, __shfl_xor_sync(0xffffffffu, rm1, 1));
        rm1 = fmaxf(rm1, __shfl_xor_sync(0xffffffffu, rm1, 2));
        float nm0 = fmaxf(m0, rm0), nm1 = fmaxf(m1, rm1);
        float corr0 = ex2(m0 - nm0), corr1 = ex2(m1 - nm1);
        m0 = nm0; m1 = nm1;

        float ps0 = 0.f, ps1 = 0.f;
#pragma unroll
        for (int nt = 0; nt < 4; nt++) {
            sc[nt][0] = ex2(sc[nt][0] - nm0);
            sc[nt][1] = ex2(sc[nt][1] - nm0);
            sc[nt][2] = ex2(sc[nt][2] - nm1);
            sc[nt][3] = ex2(sc[nt][3] - nm1);
            ps0 += sc[nt][0] + sc[nt][1];
            ps1 += sc[nt][2] + sc[nt][3];
        }
        ps0 += __shfl_xor_sync(0xffffffffu, ps0, 1);
        ps0 += __shfl_xor_sync(0xffffffffu, ps0, 2);
        ps1 += __shfl_xor_sync(0xffffffffu, ps1, 1);
        ps1 += __shfl_xor_sync(0xffffffffu, ps1, 2);
        l0 = l0 * corr0 + ps0;
        l1 = l1 * corr1 + ps1;
#pragma unroll
        for (int nt = 0; nt < 4; nt++) {
            oc[nt][0] *= corr0; oc[nt][1] *= corr0;
            oc[nt][2] *= corr1; oc[nt][3] *= corr1;
        }

        // ---- P -> split bf16 A-fragments ----
        unsigned phA[2][4], plA[2][4];
#pragma unroll
        for (int kc = 0; kc < 2; kc++)
#pragma unroll
            for (int half = 0; half < 2; half++) {
                const int nt = 2 * kc + half;
                unsigned ph0, ph1;
                PKBF(ph0, sc[nt][0], sc[nt][1]);
                PKBF(ph1, sc[nt][2], sc[nt][3]);
                float r0 = sc[nt][0] - __uint_as_float(ph0 << 16);
                float r1 = sc[nt][1] - __uint_as_float(ph0 & 0xffff0000u);
                float r2 = sc[nt][2] - __uint_as_float(ph1 << 16);
                float r3 = sc[nt][3] - __uint_as_float(ph1 & 0xffff0000u);
                unsigned pl0, pl1;
                PKBF(pl0, r0, r1);
                PKBF(pl1, r2, r3);
                phA[kc][2 * half] = ph0; phA[kc][2 * half + 1] = ph1;
                plA[kc][2 * half] = pl0; plA[kc][2 * half + 1] = pl1;
            }

        // ---- V fragments (trans) ----
        uint4 vhf[2][2], vlf[2][2];
#pragma unroll
        for (int kc = 0; kc < 2; kc++)
#pragma unroll
            for (int p = 0; p < 2; p++) {
                unsigned off = swz(kc * 16 + lb3 * 8 + l7, hb + p * 16 + lb4 * 8);
                ldsm4t(vhf[kc][p], tb + 2 * ARR + off);
                ldsm4t(vlf[kc][p], tb + 3 * ARR + off);
            }

        // ---- O += ph@vh + pl@vh + ph@vl ----
#pragma unroll
        for (int nt = 0; nt < 4; nt++) {
            const int p = nt >> 1, s = nt & 1;
#pragma unroll
            for (int kc = 0; kc < 2; kc++) {
                unsigned bh0 = s ? vhf[kc][p].z : vhf[kc][p].x;
                unsigned bh1 = s ? vhf[kc][p].w : vhf[kc][p].y;
                unsigned bl0 = s ? vlf[kc][p].z : vlf[kc][p].x;
                unsigned bl1 = s ? vlf[kc][p].w : vlf[kc][p].y;
                mma_bf16(oc[nt][0], oc[nt][1], oc[nt][2], oc[nt][3],
                         phA[kc][0], phA[kc][1], phA[kc][2], phA[kc][3], bh0, bh1);
                mma_bf16(oc[nt][0], oc[nt][1], oc[nt][2], oc[nt][3],
                         plA[kc][0], plA[kc][1], plA[kc][2], plA[kc][3], bh0, bh1);
                mma_bf16(oc[nt][0], oc[nt][1], oc[nt][2], oc[nt][3],
                         phA[kc][0], phA[kc][1], phA[kc][2], phA[kc][3], bl0, bl1);
            }
        }

        __syncthreads();
        if (tid == 0 && t < 126) stage_tile(sb, t + 2, cur);
        mw0 = nw0; mw1 = nw1;
    }

    // ---- epilogue (fp32 row-major for the Wo gemm) ----
    float inv0 = 1.f / l0, inv1 = 1.f / l1;
    float* o0 = g_att + (size_t)(qb + qoff + g) * 256 + hb;
    float* o1 = g_att + (size_t)(qb + qoff + g + 8) * 256 + hb;
#pragma unroll
    for (int nt = 0; nt < 4; nt++) {
        float2 a = {oc[nt][0] * inv0, oc[nt][1] * inv0};
        float2 b = {oc[nt][2] * inv1, oc[nt][3] * inv1};
        *(float2*)(o0 + nt * 8 + 2 * tig) = a;
        *(float2*)(o1 + nt * 8 + 2 * tig) = b;
    }
}

// ---------------------------------------------------------------------------
extern "C" void kernel_launch(void* const* d_in, const int* in_sizes, int n_in,
                              void* d_out, int out_size)
{
    (void)in_sizes; (void)n_in; (void)out_size;
    const float* x   = (const float*)d_in[0];
    const float* adj = (const float*)d_in[1];
    const float* Wq  = (const float*)d_in[2];
    const float* bq  = (const float*)d_in[3];
    const float* Wk  = (const float*)d_in[4];
    const float* bk  = (const float*)d_in[5];
    const float* Wv  = (const float*)d_in[6];
    const float* bv  = (const float*)d_in[7];
    const float* Wo  = (const float*)d_in[8];
    const float* bo  = (const float*)d_in[9];
    float* out = (float*)d_out;

    __nv_bfloat16 *qh, *ql, *kh, *kl, *vh, *vl;
    float* pa;
    cudaGetSymbolAddress((void**)&qh, g_qh);
    cudaGetSymbolAddress((void**)&ql, g_ql);
    cudaGetSymbolAddress((void**)&kh, g_kh);
    cudaGetSymbolAddress((void**)&kl, g_kl);
    cudaGetSymbolAddress((void**)&vh, g_vh);
    cudaGetSymbolAddress((void**)&vl, g_vl);
    cudaGetSymbolAddress((void**)&pa, g_att);

    cudaFuncSetAttribute(attn_kernel,
                         cudaFuncAttributeMaxDynamicSharedMemorySize, SMEM_BYTES);

    dim3 gg(64, 4);
    mask_kernel<<<2048, 256>>>(adj);
    gemm_bias_kernel<1><<<gg, 256>>>(x, Wq, bq, nullptr, qh, ql, QSCALE);
    gemm_bias_kernel<1><<<gg, 256>>>(x, Wk, bk, nullptr, kh, kl, 1.0f);
    gemm_bias_kernel<1><<<gg, 256>>>(x, Wv, bv, nullptr, vh, vl, 1.0f);
    attn_kernel<<<128, 512, SMEM_BYTES>>>();
    gemm_bias_kernel<0><<<gg, 256>>>(pa, Wo, bo, out, nullptr, nullptr, 1.0f);
}

// round 5
// speedup vs baseline: 4.6438x; 1.0541x over previous
#include <cuda_runtime.h>
#include <cuda_bf16.h>
#include <math.h>

#define NTOK 4096
#define QSCALE 0.2550760660737454f   /* (1/sqrt(32)) * log2(e) */
#define NEGL2  -1e30f

// ---- device scratch (allocation-free rule). bf16 arrays are stored in
// tile-swizzled layout: tile = row>>5 (16KB blocks), within tile the 16B
// chunk index is (col>>3) ^ (row&7)  -> conflict-free ldmatrix after a raw
// 1D bulk copy into smem.
static __device__ __align__(1024) float g_att[NTOK * 256];
static __device__ __align__(1024) __nv_bfloat16 g_qh[NTOK * 256], g_ql[NTOK * 256];
static __device__ __align__(1024) __nv_bfloat16 g_kh[NTOK * 256], g_kl[NTOK * 256];
static __device__ __align__(1024) __nv_bfloat16 g_vh[NTOK * 256], g_vl[NTOK * 256];
static __device__ __align__(1024) unsigned g_amask[128 * NTOK];   // [tile][q]

// ---------------- helpers ----------------
__device__ __forceinline__ float ex2(float x) {
    float r;
    asm("ex2.approx.ftz.f32 %0, %1;" : "=f"(r) : "f"(x));
    return r;
}
// d = bf16x2{hi, lo}
#define PKBF(d, lo, hi) \
    asm("cvt.rn.bf16x2.f32 %0, %1, %2;" : "=r"(d) : "f"(hi), "f"(lo))

__device__ __forceinline__ void ldsm4(uint4& r, unsigned addr) {
    asm volatile("ldmatrix.sync.aligned.m8n8.x4.shared.b16 {%0,%1,%2,%3}, [%4];"
                 : "=r"(r.x), "=r"(r.y), "=r"(r.z), "=r"(r.w) : "r"(addr));
}
__device__ __forceinline__ void ldsm4t(uint4& r, unsigned addr) {
    asm volatile("ldmatrix.sync.aligned.m8n8.x4.trans.shared.b16 {%0,%1,%2,%3}, [%4];"
                 : "=r"(r.x), "=r"(r.y), "=r"(r.z), "=r"(r.w) : "r"(addr));
}
__device__ __forceinline__ void mma_bf16(
    float& d0, float& d1, float& d2, float& d3,
    unsigned a0, unsigned a1, unsigned a2, unsigned a3,
    unsigned b0, unsigned b1)
{
    asm("mma.sync.aligned.m16n8k16.row.col.f32.bf16.bf16.f32 "
        "{%0,%1,%2,%3},{%4,%5,%6,%7},{%8,%9},{%0,%1,%2,%3};"
        : "+f"(d0), "+f"(d1), "+f"(d2), "+f"(d3)
        : "r"(a0), "r"(a1), "r"(a2), "r"(a3), "r"(b0), "r"(b1));
}

__device__ __forceinline__ void mbar_init(unsigned addr, unsigned cnt) {
    asm volatile("mbarrier.init.shared.b64 [%0], %1;" :: "r"(addr), "r"(cnt) : "memory");
}
__device__ __forceinline__ void mbar_expect(unsigned addr, unsigned tx) {
    asm volatile("mbarrier.arrive.expect_tx.shared.b64 _, [%0], %1;"
                 :: "r"(addr), "r"(tx) : "memory");
}
__device__ __forceinline__ void mbar_wait(unsigned addr, unsigned phase) {
    unsigned done = 0;
    while (!done) {
        asm volatile(
            "{\n .reg .pred p;\n"
            " mbarrier.try_wait.parity.acquire.cta.shared::cta.b64 p, [%1], %2, 0x989680;\n"
            " selp.b32 %0, 1, 0, p;\n}"
            : "=r"(done) : "r"(addr), "r"(phase) : "memory");
    }
}
__device__ __forceinline__ void bulkcp(unsigned dst, const void* src,
                                       unsigned bytes, unsigned mbar) {
    unsigned long long ga;
    asm("cvta.to.global.u64 %0, %1;" : "=l"(ga) : "l"(src));
    asm volatile(
        "cp.async.bulk.shared::cta.global.mbarrier::complete_tx::bytes "
        "[%0], [%1], %2, [%3];"
        :: "r"(dst), "l"(ga), "r"(bytes), "r"(mbar) : "memory");
}

// swizzled byte offset within a 32x512B tile block
__device__ __forceinline__ unsigned swz(int row, int colbf16) {
    return (unsigned)(row * 512 + ((((colbf16 >> 3) ^ (row & 7))) << 4)
                      + ((colbf16 & 7) << 1));
}

// split v into hi/lo bf16 and store swizzled
__device__ __forceinline__ void store_hilo(
    float v0, float v1, float v2, float v3, int row, int col,
    __nv_bfloat16* __restrict__ Ch, __nv_bfloat16* __restrict__ Cl)
{
    unsigned hp0, hp1, lp0, lp1;
    PKBF(hp0, v0, v1);
    PKBF(hp1, v2, v3);
    float r0 = v0 - __uint_as_float(hp0 << 16);
    float r1 = v1 - __uint_as_float(hp0 & 0xffff0000u);
    float r2 = v2 - __uint_as_float(hp1 << 16);
    float r3 = v3 - __uint_as_float(hp1 & 0xffff0000u);
    PKBF(lp0, r0, r1);
    PKBF(lp1, r2, r3);
    unsigned off = ((unsigned)(row >> 5) << 14) + swz(row & 31, col);
    uint2 hw = {hp0, hp1}, lw = {lp0, lp1};
    *(uint2*)((char*)Ch + off) = hw;
    *(uint2*)((char*)Cl + off) = lw;
}

// ---------------------------------------------------------------------------
// adj -> bitmask, coalesced: one warp per query row.
// g_amask[t*4096 + q] bit j = adj[q][t*32+j] > 0
// ---------------------------------------------------------------------------
__global__ __launch_bounds__(256) void mask_kernel(const float* __restrict__ adj)
{
    const int q = (blockIdx.x << 3) + (threadIdx.x >> 5);   // warp-per-row
    const int lane = threadIdx.x & 31;
    const float* row = adj + (size_t)q * NTOK + lane;
#pragma unroll 4
    for (int t = 0; t < 128; t++) {
        float v = row[t << 5];
        unsigned w = __ballot_sync(0xffffffffu, v > 0.f);
        if (lane == 0) g_amask[t * NTOK + q] = w;
    }
}

// ---------------------------------------------------------------------------
// Fused Q/K/V projection: one A tile feeds three weight matrices.
// Tiles 64x64, grid (64,4), 256 threads, 4x4 micro-tile x 3 outputs.
// Outputs hi/lo bf16, tile-swizzled; Q pre-scaled by QSCALE.
// ---------------------------------------------------------------------------
__global__ __launch_bounds__(256) void gemm_qkv_kernel(
    const float* __restrict__ A,
    const float* __restrict__ Wq, const float* __restrict__ bq,
    const float* __restrict__ Wk, const float* __restrict__ bk,
    const float* __restrict__ Wv, const float* __restrict__ bv)
{
    __shared__ float As[16][68];
    __shared__ float Bs[3][16][68];

    const int tid = threadIdx.x;
    const int tx = tid & 15;
    const int ty = tid >> 4;
    const int mb = blockIdx.x * 64;
    const int nb = blockIdx.y * 64;

    const int arow = tid >> 2;
    const int ac4  = (tid & 3) << 2;
    const int brow = tid >> 4;
    const int bc4  = (tid & 15) << 2;

    float acc[3][4][4];
#pragma unroll
    for (int s = 0; s < 3; s++)
#pragma unroll
        for (int i = 0; i < 4; i++)
#pragma unroll
            for (int j = 0; j < 4; j++) acc[s][i][j] = 0.f;

    const float* Ws[3] = {Wq, Wk, Wv};

    for (int kb = 0; kb < 256; kb += 16) {
        float4 av = *(const float4*)&A[(mb + arow) * 256 + kb + ac4];
        float4 w0 = *(const float4*)&Ws[0][(kb + brow) * 256 + nb + bc4];
        float4 w1 = *(const float4*)&Ws[1][(kb + brow) * 256 + nb + bc4];
        float4 w2 = *(const float4*)&Ws[2][(kb + brow) * 256 + nb + bc4];
        __syncthreads();
        As[ac4 + 0][arow] = av.x;
        As[ac4 + 1][arow] = av.y;
        As[ac4 + 2][arow] = av.z;
        As[ac4 + 3][arow] = av.w;
        *(float4*)&Bs[0][brow][bc4] = w0;
        *(float4*)&Bs[1][brow][bc4] = w1;
        *(float4*)&Bs[2][brow][bc4] = w2;
        __syncthreads();
#pragma unroll
        for (int kk = 0; kk < 16; kk++) {
            float4 a = *(float4*)&As[kk][ty << 2];
            float a4[4] = {a.x, a.y, a.z, a.w};
#pragma unroll
            for (int s = 0; s < 3; s++) {
                float4 b = *(float4*)&Bs[s][kk][tx << 2];
                float b4[4] = {b.x, b.y, b.z, b.w};
#pragma unroll
                for (int i = 0; i < 4; i++)
#pragma unroll
                    for (int j = 0; j < 4; j++)
                        acc[s][i][j] += a4[i] * b4[j];
            }
        }
    }

    float4 bvq = *(const float4*)&bq[nb + (tx << 2)];
    float4 bvk = *(const float4*)&bk[nb + (tx << 2)];
    float4 bvv = *(const float4*)&bv[nb + (tx << 2)];
#pragma unroll
    for (int i = 0; i < 4; i++) {
        int row = mb + (ty << 2) + i;
        int col = nb + (tx << 2);
        store_hilo((acc[0][i][0] + bvq.x) * QSCALE, (acc[0][i][1] + bvq.y) * QSCALE,
                   (acc[0][i][2] + bvq.z) * QSCALE, (acc[0][i][3] + bvq.w) * QSCALE,
                   row, col, g_qh, g_ql);
        store_hilo(acc[1][i][0] + bvk.x, acc[1][i][1] + bvk.y,
                   acc[1][i][2] + bvk.z, acc[1][i][3] + bvk.w,
                   row, col, g_kh, g_kl);
        store_hilo(acc[2][i][0] + bvv.x, acc[2][i][1] + bvv.y,
                   acc[2][i][2] + bvv.z, acc[2][i][3] + bvv.w,
                   row, col, g_vh, g_vl);
    }
}

// ---------------------------------------------------------------------------
// Output GEMM: out = g_att[4096,256] @ Wo + bo   (fp32, row-major out)
// ---------------------------------------------------------------------------
__global__ __launch_bounds__(256) void gemm_out_kernel(
    const float* __restrict__ A, const float* __restrict__ W,
    const float* __restrict__ bias, float* __restrict__ C)
{
    __shared__ float As[16][68];
    __shared__ float Bs[16][68];

    const int tid = threadIdx.x;
    const int tx = tid & 15;
    const int ty = tid >> 4;
    const int mb = blockIdx.x * 64;
    const int nb = blockIdx.y * 64;

    const int arow = tid >> 2;
    const int ac4  = (tid & 3) << 2;
    const int brow = tid >> 4;
    const int bc4  = (tid & 15) << 2;

    float acc[4][4];
#pragma unroll
    for (int i = 0; i < 4; i++)
#pragma unroll
        for (int j = 0; j < 4; j++) acc[i][j] = 0.f;

    for (int kb = 0; kb < 256; kb += 16) {
        float4 av = *(const float4*)&A[(mb + arow) * 256 + kb + ac4];
        float4 wv = *(const float4*)&W[(kb + brow) * 256 + nb + bc4];
        __syncthreads();
        As[ac4 + 0][arow] = av.x;
        As[ac4 + 1][arow] = av.y;
        As[ac4 + 2][arow] = av.z;
        As[ac4 + 3][arow] = av.w;
        *(float4*)&Bs[brow][bc4] = wv;
        __syncthreads();
#pragma unroll
        for (int kk = 0; kk < 16; kk++) {
            float4 a = *(float4*)&As[kk][ty << 2];
            float4 b = *(float4*)&Bs[kk][tx << 2];
            float a4[4] = {a.x, a.y, a.z, a.w};
            float b4[4] = {b.x, b.y, b.z, b.w};
#pragma unroll
            for (int i = 0; i < 4; i++)
#pragma unroll
                for (int j = 0; j < 4; j++)
                    acc[i][j] += a4[i] * b4[j];
        }
    }

    float4 bv = *(const float4*)&bias[nb + (tx << 2)];
#pragma unroll
    for (int i = 0; i < 4; i++) {
        float4 o;
        o.x = acc[i][0] + bv.x;
        o.y = acc[i][1] + bv.y;
        o.z = acc[i][2] + bv.z;
        o.w = acc[i][3] + bv.w;
        *(float4*)&C[(mb + (ty << 2) + i) * 256 + nb + (tx << 2)] = o;
    }
}

// ---------------------------------------------------------------------------
// Tensor-core flash attention (unchanged from round 4).
// Block = 512 threads / 16 warps: warp w -> head w&7, q-half w>>3.
// 32 queries/block, key tile 32, grid 128, TMA-bulk double buffering.
// ---------------------------------------------------------------------------
#define QH_OFF 0
#define QL_OFF 16384
#define TILE_OFF 32768
#define ARR 16384
#define BUF 65536
#define BAR_OFF 163840
#define SMEM_BYTES 163872

__device__ __forceinline__ void stage_tile(unsigned sb, int t, int buf) {
    unsigned bar = sb + BAR_OFF + buf * 8;
    unsigned base = sb + TILE_OFF + buf * BUF;
    size_t go = (size_t)t << 14;
    mbar_expect(bar, 4 * ARR);
    bulkcp(base,           (const char*)g_kh + go, ARR, bar);
    bulkcp(base + ARR,     (const char*)g_kl + go, ARR, bar);
    bulkcp(base + 2 * ARR, (const char*)g_vh + go, ARR, bar);
    bulkcp(base + 3 * ARR, (const char*)g_vl + go, ARR, bar);
}

__global__ __launch_bounds__(512, 1) void attn_kernel()
{
    extern __shared__ char smc[];
    unsigned sb = (unsigned)__cvta_generic_to_shared(smc);

    const int tid = threadIdx.x;
    const int lane = tid & 31;
    const int w = tid >> 5;
    const int hb = (w & 7) << 5;          // head's bf16 col base
    const int qoff = (w >> 3) << 4;       // 0 or 16
    const int qb = blockIdx.x << 5;
    const int g = lane >> 2, tig = lane & 3;
    const int l7 = lane & 7, lb3 = (lane >> 3) & 1, lb4 = lane >> 4;

    if (tid == 0) {
        mbar_init(sb + BAR_OFF, 1);
        mbar_init(sb + BAR_OFF + 8, 1);
        mbar_init(sb + BAR_OFF + 16, 1);
        asm volatile("fence.proxy.async.shared::cta;" ::: "memory");
    }
    __syncthreads();
    if (tid == 0) {
        unsigned qbar = sb + BAR_OFF + 16;
        size_t go = (size_t)blockIdx.x << 14;
        mbar_expect(qbar, 2 * ARR);
        bulkcp(sb + QH_OFF, (const char*)g_qh + go, ARR, qbar);
        bulkcp(sb + QL_OFF, (const char*)g_ql + go, ARR, qbar);
        stage_tile(sb, 0, 0);
        stage_tile(sb, 1, 1);
    }

    // mask prefetch (tile 0)
    const unsigned* am = g_amask + qb + qoff + g;
    unsigned mw0 = __ldg(am);
    unsigned mw1 = __ldg(am + 8);

    mbar_wait(sb + BAR_OFF + 16, 0);

    // Q fragments, kept in registers for whole kernel
    unsigned qhf[2][4], qlf[2][4];
#pragma unroll
    for (int kc = 0; kc < 2; kc++) {
        unsigned off = swz(qoff + (lane & 15), hb + kc * 16 + ((lane >> 4) << 3));
        uint4 r;
        ldsm4(r, sb + QH_OFF + off);
        qhf[kc][0] = r.x; qhf[kc][1] = r.y; qhf[kc][2] = r.z; qhf[kc][3] = r.w;
        ldsm4(r, sb + QL_OFF + off);
        qlf[kc][0] = r.x; qlf[kc][1] = r.y; qlf[kc][2] = r.z; qlf[kc][3] = r.w;
    }

    float oc[4][4];
#pragma unroll
    for (int i = 0; i < 4; i++)
#pragma unroll
        for (int j = 0; j < 4; j++) oc[i][j] = 0.f;
    float m0 = NEGL2, m1 = NEGL2, l0 = 0.f, l1 = 0.f;

    for (int t = 0; t < 128; t++) {
        unsigned nw0 = 0, nw1 = 0;
        if (t < 127) {
            nw0 = __ldg(am + (t + 1) * NTOK);
            nw1 = __ldg(am + (t + 1) * NTOK + 8);
        }
        const int cur = t & 1;
        mbar_wait(sb + BAR_OFF + cur * 8, (t >> 1) & 1);
        const unsigned tb = sb + TILE_OFF + cur * BUF;

        // ---- K fragments ----
        uint4 khf[2][2], klf[2][2];
#pragma unroll
        for (int kc = 0; kc < 2; kc++)
#pragma unroll
            for (int p = 0; p < 2; p++) {
                unsigned off = swz(16 * p + lb4 * 8 + l7, hb + kc * 16 + lb3 * 8);
                ldsm4(khf[kc][p], tb + off);
                ldsm4(klf[kc][p], tb + ARR + off);
            }

        // ---- S = qh@kh + ql@kh + qh@kl ----
        float sc[4][4];
#pragma unroll
        for (int i = 0; i < 4; i++)
#pragma unroll
            for (int j = 0; j < 4; j++) sc[i][j] = 0.f;
#pragma unroll
        for (int nt = 0; nt < 4; nt++) {
            const int p = nt >> 1, s = nt & 1;
#pragma unroll
            for (int kc = 0; kc < 2; kc++) {
                unsigned bh0 = s ? khf[kc][p].z : khf[kc][p].x;
                unsigned bh1 = s ? khf[kc][p].w : khf[kc][p].y;
                unsigned bl0 = s ? klf[kc][p].z : klf[kc][p].x;
                unsigned bl1 = s ? klf[kc][p].w : klf[kc][p].y;
                mma_bf16(sc[nt][0], sc[nt][1], sc[nt][2], sc[nt][3],
                         qhf[kc][0], qhf[kc][1], qhf[kc][2], qhf[kc][3], bh0, bh1);
                mma_bf16(sc[nt][0], sc[nt][1], sc[nt][2], sc[nt][3],
                         qlf[kc][0], qlf[kc][1], qlf[kc][2], qlf[kc][3], bh0, bh1);
                mma_bf16(sc[nt][0], sc[nt][1], sc[nt][2], sc[nt][3],
                         qhf[kc][0], qhf[kc][1], qhf[kc][2], qhf[kc][3], bl0, bl1);
            }
        }

        // ---- mask + online softmax (log2 domain; q pre-scaled) ----
        float rm0 = NEGL2, rm1 = NEGL2;
#pragma unroll
        for (int nt = 0; nt < 4; nt++) {
            int j0 = nt * 8 + 2 * tig;
            sc[nt][0] = ((mw0 >> j0) & 1) ? sc[nt][0] : NEGL2;
            sc[nt][1] = ((mw0 >> (j0 + 1)) & 1) ? sc[nt][1] : NEGL2;
            sc[nt][2] = ((mw1 >> j0) & 1) ? sc[nt][2] : NEGL2;
            sc[nt][3] = ((mw1 >> (j0 + 1)) & 1) ? sc[nt][3] : NEGL2;
            rm0 = fmaxf(rm0, fmaxf(sc[nt][0], sc[nt][1]));
            rm1 = fmaxf(rm1, fmaxf(sc[nt][2], sc[nt][3]));
        }
        rm0 = fmaxf(rm0, __shfl_xor_sync(0xffffffffu, rm0, 1));
        rm0 = fmaxf(rm0, __shfl_xor_sync(0xffffffffu, rm0, 2));
        rm1 = fmaxf(rm1, __shfl_xor_sync(0xffffffffu, rm1, 1));
        rm1 = fmaxf(rm1, __shfl_xor_sync(0xffffffffu, rm1, 2));
        float nm0 = fmaxf(m0, rm0), nm1 = fmaxf(m1, rm1);
        float corr0 = ex2(m0 - nm0), corr1 = ex2(m1 - nm1);
        m0 = nm0; m1 = nm1;

        float ps0 = 0.f, ps1 = 0.f;
#pragma unroll
        for (int nt = 0; nt < 4; nt++) {
            sc[nt][0] = ex2(sc[nt][0] - nm0);
            sc[nt][1] = ex2(sc[nt][1] - nm0);
            sc[nt][2] = ex2(sc[nt][2] - nm1);
            sc[nt][3] = ex2(sc[nt][3] - nm1);
            ps0 += sc[nt][0] + sc[nt][1];
            ps1 += sc[nt][2] + sc[nt][3];
        }
        ps0 += __shfl_xor_sync(0xffffffffu, ps0, 1);
        ps0 += __shfl_xor_sync(0xffffffffu, ps0, 2);
        ps1 += __shfl_xor_sync(0xffffffffu, ps1, 1);
        ps1 += __shfl_xor_sync(0xffffffffu, ps1, 2);
        l0 = l0 * corr0 + ps0;
        l1 = l1 * corr1 + ps1;
#pragma unroll
        for (int nt = 0; nt < 4; nt++) {
            oc[nt][0] *= corr0; oc[nt][1] *= corr0;
            oc[nt][2] *= corr1; oc[nt][3] *= corr1;
        }

        // ---- P -> split bf16 A-fragments ----
        unsigned phA[2][4], plA[2][4];
#pragma unroll
        for (int kc = 0; kc < 2; kc++)
#pragma unroll
            for (int half = 0; half < 2; half++) {
                const int nt = 2 * kc + half;
                unsigned ph0, ph1;
                PKBF(ph0, sc[nt][0], sc[nt][1]);
                PKBF(ph1, sc[nt][2], sc[nt][3]);
                float r0 = sc[nt][0] - __uint_as_float(ph0 << 16);
                float r1 = sc[nt][1] - __uint_as_float(ph0 & 0xffff0000u);
                float r2 = sc[nt][2] - __uint_as_float(ph1 << 16);
                float r3 = sc[nt][3] - __uint_as_float(ph1 & 0xffff0000u);
                unsigned pl0, pl1;
                PKBF(pl0, r0, r1);
                PKBF(pl1, r2, r3);
                phA[kc][2 * half] = ph0; phA[kc][2 * half + 1] = ph1;
                plA[kc][2 * half] = pl0; plA[kc][2 * half + 1] = pl1;
            }

        // ---- V fragments (trans) ----
        uint4 vhf[2][2], vlf[2][2];
#pragma unroll
        for (int kc = 0; kc < 2; kc++)
#pragma unroll
            for (int p = 0; p < 2; p++) {
                unsigned off = swz(kc * 16 + lb3 * 8 + l7, hb + p * 16 + lb4 * 8);
                ldsm4t(vhf[kc][p], tb + 2 * ARR + off);
                ldsm4t(vlf[kc][p], tb + 3 * ARR + off);
            }

        // ---- O += ph@vh + pl@vh + ph@vl ----
#pragma unroll
        for (int nt = 0; nt < 4; nt++) {
            const int p = nt >> 1, s = nt & 1;
#pragma unroll
            for (int kc = 0; kc < 2; kc++) {
                unsigned bh0 = s ? vhf[kc][p].z : vhf[kc][p].x;
                unsigned bh1 = s ? vhf[kc][p].w : vhf[kc][p].y;
                unsigned bl0 = s ? vlf[kc][p].z : vlf[kc][p].x;
                unsigned bl1 = s ? vlf[kc][p].w : vlf[kc][p].y;
                mma_bf16(oc[nt][0], oc[nt][1], oc[nt][2], oc[nt][3],
                         phA[kc][0], phA[kc][1], phA[kc][2], phA[kc][3], bh0, bh1);
                mma_bf16(oc[nt][0], oc[nt][1], oc[nt][2], oc[nt][3],
                         plA[kc][0], plA[kc][1], plA[kc][2], plA[kc][3], bh0, bh1);
                mma_bf16(oc[nt][0], oc[nt][1], oc[nt][2], oc[nt][3],
                         phA[kc][0], phA[kc][1], phA[kc][2], phA[kc][3], bl0, bl1);
            }
        }

        __syncthreads();
        if (tid == 0 && t < 126) stage_tile(sb, t + 2, cur);
        mw0 = nw0; mw1 = nw1;
    }

    // ---- epilogue (fp32 row-major for the Wo gemm) ----
    float inv0 = 1.f / l0, inv1 = 1.f / l1;
    float* o0 = g_att + (size_t)(qb + qoff + g) * 256 + hb;
    float* o1 = g_att + (size_t)(qb + qoff + g + 8) * 256 + hb;
#pragma unroll
    for (int nt = 0; nt < 4; nt++) {
        float2 a = {oc[nt][0] * inv0, oc[nt][1] * inv0};
        float2 b = {oc[nt][2] * inv1, oc[nt][3] * inv1};
        *(float2*)(o0 + nt * 8 + 2 * tig) = a;
        *(float2*)(o1 + nt * 8 + 2 * tig) = b;
    }
}

// ---------------------------------------------------------------------------
extern "C" void kernel_launch(void* const* d_in, const int* in_sizes, int n_in,
                              void* d_out, int out_size)
{
    (void)in_sizes; (void)n_in; (void)out_size;
    const float* x   = (const float*)d_in[0];
    const float* adj = (const float*)d_in[1];
    const float* Wq  = (const float*)d_in[2];
    const float* bq  = (const float*)d_in[3];
    const float* Wk  = (const float*)d_in[4];
    const float* bk  = (const float*)d_in[5];
    const float* Wv  = (const float*)d_in[6];
    const float* bv  = (const float*)d_in[7];
    const float* Wo  = (const float*)d_in[8];
    const float* bo  = (const float*)d_in[9];
    float* out = (float*)d_out;

    float* pa;
    cudaGetSymbolAddress((void**)&pa, g_att);

    cudaFuncSetAttribute(attn_kernel,
                         cudaFuncAttributeMaxDynamicSharedMemorySize, SMEM_BYTES);

    dim3 gg(64, 4);
    mask_kernel<<<512, 256>>>(adj);
    gemm_qkv_kernel<<<gg, 256>>>(x, Wq, bq, Wk, bk, Wv, bv);
    attn_kernel<<<128, 512, SMEM_BYTES>>>();
    gemm_out_kernel<<<gg, 256>>>(pa, Wo, bo, out);
}

// round 6
// speedup vs baseline: 8.0160x; 1.7262x over previous
#include <cuda_runtime.h>
#include <cuda_fp16.h>
#include <math.h>

#define NTOK 4096
#define QSCALE 0.2550760660737454f   /* (1/sqrt(32)) * log2(e) */
#define NEGL2  -1e30f

// ---- device scratch (allocation-free rule). fp16 arrays tile-swizzled:
// tile = row>>5 (16KB blocks), within tile 16B-chunk index = (col>>3)^(row&7).
static __device__ __align__(1024) float g_att[NTOK * 256];
static __device__ __align__(1024) __half g_q16[NTOK * 256];
static __device__ __align__(1024) __half g_k16[NTOK * 256];
static __device__ __align__(1024) __half g_v16[NTOK * 256];
static __device__ __align__(1024) unsigned g_amask[128 * NTOK];   // [tile][q]

// ---------------- helpers ----------------
// d(f16x2) = {lo, hi} from two f32
#define PKH(d, lo, hi) \
    asm("cvt.rn.f16x2.f32 %0, %1, %2;" : "=r"(d) : "f"(hi), "f"(lo))
#define EX2H2(d, a) \
    asm("ex2.approx.f16x2 %0, %1;" : "=r"(d) : "r"(a))

__device__ __forceinline__ void ldsm4(uint4& r, unsigned addr) {
    asm volatile("ldmatrix.sync.aligned.m8n8.x4.shared.b16 {%0,%1,%2,%3}, [%4];"
                 : "=r"(r.x), "=r"(r.y), "=r"(r.z), "=r"(r.w) : "r"(addr));
}
__device__ __forceinline__ void ldsm4t(uint4& r, unsigned addr) {
    asm volatile("ldmatrix.sync.aligned.m8n8.x4.trans.shared.b16 {%0,%1,%2,%3}, [%4];"
                 : "=r"(r.x), "=r"(r.y), "=r"(r.z), "=r"(r.w) : "r"(addr));
}
__device__ __forceinline__ void mma_f16(
    float& d0, float& d1, float& d2, float& d3,
    unsigned a0, unsigned a1, unsigned a2, unsigned a3,
    unsigned b0, unsigned b1)
{
    asm("mma.sync.aligned.m16n8k16.row.col.f32.f16.f16.f32 "
        "{%0,%1,%2,%3},{%4,%5,%6,%7},{%8,%9},{%0,%1,%2,%3};"
        : "+f"(d0), "+f"(d1), "+f"(d2), "+f"(d3)
        : "r"(a0), "r"(a1), "r"(a2), "r"(a3), "r"(b0), "r"(b1));
}

__device__ __forceinline__ void mbar_init(unsigned addr, unsigned cnt) {
    asm volatile("mbarrier.init.shared.b64 [%0], %1;" :: "r"(addr), "r"(cnt) : "memory");
}
__device__ __forceinline__ void mbar_expect(unsigned addr, unsigned tx) {
    asm volatile("mbarrier.arrive.expect_tx.shared.b64 _, [%0], %1;"
                 :: "r"(addr), "r"(tx) : "memory");
}
__device__ __forceinline__ void mbar_wait(unsigned addr, unsigned phase) {
    unsigned done = 0;
    while (!done) {
        asm volatile(
            "{\n .reg .pred p;\n"
            " mbarrier.try_wait.parity.acquire.cta.shared::cta.b64 p, [%1], %2, 0x989680;\n"
            " selp.b32 %0, 1, 0, p;\n}"
            : "=r"(done) : "r"(addr), "r"(phase) : "memory");
    }
}
__device__ __forceinline__ void bulkcp(unsigned dst, const void* src,
                                       unsigned bytes, unsigned mbar) {
    unsigned long long ga;
    asm("cvta.to.global.u64 %0, %1;" : "=l"(ga) : "l"(src));
    asm volatile(
        "cp.async.bulk.shared::cta.global.mbarrier::complete_tx::bytes "
        "[%0], [%1], %2, [%3];"
        :: "r"(dst), "l"(ga), "r"(bytes), "r"(mbar) : "memory");
}

// swizzled byte offset within a 32x512B tile block (2-byte elements)
__device__ __forceinline__ unsigned swz(int row, int col) {
    return (unsigned)(row * 512 + ((((col >> 3) ^ (row & 7))) << 4)
                      + ((col & 7) << 1));
}

// ---------------------------------------------------------------------------
// adj -> bitmask, coalesced: one warp per query row.
// ---------------------------------------------------------------------------
__global__ __launch_bounds__(256) void mask_kernel(const float* __restrict__ adj)
{
    const int q = (blockIdx.x << 3) + (threadIdx.x >> 5);
    const int lane = threadIdx.x & 31;
    const float* row = adj + (size_t)q * NTOK + lane;
#pragma unroll 4
    for (int t = 0; t < 128; t++) {
        float v = row[t << 5];
        unsigned w = __ballot_sync(0xffffffffu, v > 0.f);
        if (lane == 0) g_amask[t * NTOK + q] = w;
    }
}

// ---------------------------------------------------------------------------
// Fused Q/K/V projection, fp16 swizzled outputs (Q pre-scaled by QSCALE).
// ---------------------------------------------------------------------------
__device__ __forceinline__ void store_h4(
    float v0, float v1, float v2, float v3, int row, int col, __half* C)
{
    unsigned p0, p1;
    PKH(p0, v0, v1);
    PKH(p1, v2, v3);
    unsigned off = ((unsigned)(row >> 5) << 14) + swz(row & 31, col);
    uint2 w = {p0, p1};
    *(uint2*)((char*)C + off) = w;
}

__global__ __launch_bounds__(256) void gemm_qkv_kernel(
    const float* __restrict__ A,
    const float* __restrict__ Wq, const float* __restrict__ bq,
    const float* __restrict__ Wk, const float* __restrict__ bk,
    const float* __restrict__ Wv, const float* __restrict__ bv)
{
    __shared__ float As[16][68];
    __shared__ float Bs[3][16][68];

    const int tid = threadIdx.x;
    const int tx = tid & 15;
    const int ty = tid >> 4;
    const int mb = blockIdx.x * 64;
    const int nb = blockIdx.y * 64;

    const int arow = tid >> 2;
    const int ac4  = (tid & 3) << 2;
    const int brow = tid >> 4;
    const int bc4  = (tid & 15) << 2;

    float acc[3][4][4];
#pragma unroll
    for (int s = 0; s < 3; s++)
#pragma unroll
        for (int i = 0; i < 4; i++)
#pragma unroll
            for (int j = 0; j < 4; j++) acc[s][i][j] = 0.f;

    const float* Ws[3] = {Wq, Wk, Wv};

    for (int kb = 0; kb < 256; kb += 16) {
        float4 av = *(const float4*)&A[(mb + arow) * 256 + kb + ac4];
        float4 w0 = *(const float4*)&Ws[0][(kb + brow) * 256 + nb + bc4];
        float4 w1 = *(const float4*)&Ws[1][(kb + brow) * 256 + nb + bc4];
        float4 w2 = *(const float4*)&Ws[2][(kb + brow) * 256 + nb + bc4];
        __syncthreads();
        As[ac4 + 0][arow] = av.x;
        As[ac4 + 1][arow] = av.y;
        As[ac4 + 2][arow] = av.z;
        As[ac4 + 3][arow] = av.w;
        *(float4*)&Bs[0][brow][bc4] = w0;
        *(float4*)&Bs[1][brow][bc4] = w1;
        *(float4*)&Bs[2][brow][bc4] = w2;
        __syncthreads();
#pragma unroll
        for (int kk = 0; kk < 16; kk++) {
            float4 a = *(float4*)&As[kk][ty << 2];
            float a4[4] = {a.x, a.y, a.z, a.w};
#pragma unroll
            for (int s = 0; s < 3; s++) {
                float4 b = *(float4*)&Bs[s][kk][tx << 2];
                float b4[4] = {b.x, b.y, b.z, b.w};
#pragma unroll
                for (int i = 0; i < 4; i++)
#pragma unroll
                    for (int j = 0; j < 4; j++)
                        acc[s][i][j] += a4[i] * b4[j];
            }
        }
    }

    float4 bvq = *(const float4*)&bq[nb + (tx << 2)];
    float4 bvk = *(const float4*)&bk[nb + (tx << 2)];
    float4 bvv = *(const float4*)&bv[nb + (tx << 2)];
#pragma unroll
    for (int i = 0; i < 4; i++) {
        int row = mb + (ty << 2) + i;
        int col = nb + (tx << 2);
        store_h4((acc[0][i][0] + bvq.x) * QSCALE, (acc[0][i][1] + bvq.y) * QSCALE,
                 (acc[0][i][2] + bvq.z) * QSCALE, (acc[0][i][3] + bvq.w) * QSCALE,
                 row, col, g_q16);
        store_h4(acc[1][i][0] + bvk.x, acc[1][i][1] + bvk.y,
                 acc[1][i][2] + bvk.z, acc[1][i][3] + bvk.w, row, col, g_k16);
        store_h4(acc[2][i][0] + bvv.x, acc[2][i][1] + bvv.y,
                 acc[2][i][2] + bvv.z, acc[2][i][3] + bvv.w, row, col, g_v16);
    }
}

// ---------------------------------------------------------------------------
// Output GEMM: out = g_att @ Wo + bo (fp32)
// ---------------------------------------------------------------------------
__global__ __launch_bounds__(256) void gemm_out_kernel(
    const float* __restrict__ A, const float* __restrict__ W,
    const float* __restrict__ bias, float* __restrict__ C)
{
    __shared__ float As[16][68];
    __shared__ float Bs[16][68];

    const int tid = threadIdx.x;
    const int tx = tid & 15;
    const int ty = tid >> 4;
    const int mb = blockIdx.x * 64;
    const int nb = blockIdx.y * 64;

    const int arow = tid >> 2;
    const int ac4  = (tid & 3) << 2;
    const int brow = tid >> 4;
    const int bc4  = (tid & 15) << 2;

    float acc[4][4];
#pragma unroll
    for (int i = 0; i < 4; i++)
#pragma unroll
        for (int j = 0; j < 4; j++) acc[i][j] = 0.f;

    for (int kb = 0; kb < 256; kb += 16) {
        float4 av = *(const float4*)&A[(mb + arow) * 256 + kb + ac4];
        float4 wv = *(const float4*)&W[(kb + brow) * 256 + nb + bc4];
        __syncthreads();
        As[ac4 + 0][arow] = av.x;
        As[ac4 + 1][arow] = av.y;
        As[ac4 + 2][arow] = av.z;
        As[ac4 + 3][arow] = av.w;
        *(float4*)&Bs[brow][bc4] = wv;
        __syncthreads();
#pragma unroll
        for (int kk = 0; kk < 16; kk++) {
            float4 a = *(float4*)&As[kk][ty << 2];
            float4 b = *(float4*)&Bs[kk][tx << 2];
            float a4[4] = {a.x, a.y, a.z, a.w};
            float b4[4] = {b.x, b.y, b.z, b.w};
#pragma unroll
            for (int i = 0; i < 4; i++)
#pragma unroll
                for (int j = 0; j < 4; j++)
                    acc[i][j] += a4[i] * b4[j];
        }
    }

    float4 bv = *(const float4*)&bias[nb + (tx << 2)];
#pragma unroll
    for (int i = 0; i < 4; i++) {
        float4 o;
        o.x = acc[i][0] + bv.x;
        o.y = acc[i][1] + bv.y;
        o.z = acc[i][2] + bv.z;
        o.w = acc[i][3] + bv.w;
        *(float4*)&C[(mb + (ty << 2) + i) * 256 + nb + (tx << 2)] = o;
    }
}

// ---------------------------------------------------------------------------
// fp16 tensor-core flash attention with fixed softmax shift (m == 0).
// Block = 512 threads / 16 warps: warp w -> head w&7, q-half w>>3.
// 32 queries/block, key tile 32, grid 128, TMA-bulk double buffering.
// ---------------------------------------------------------------------------
#define Q_OFF 0
#define TILE_OFF 16384
#define ARR 16384
#define BUF 32768
#define BAR_OFF 81920
#define SMEM_BYTES 81952

__device__ __forceinline__ void stage_tile(unsigned sb, int t, int buf) {
    unsigned bar = sb + BAR_OFF + buf * 8;
    unsigned base = sb + TILE_OFF + buf * BUF;
    size_t go = (size_t)t << 14;
    mbar_expect(bar, 2 * ARR);
    bulkcp(base,       (const char*)g_k16 + go, ARR, bar);
    bulkcp(base + ARR, (const char*)g_v16 + go, ARR, bar);
}

__global__ __launch_bounds__(512, 1) void attn_kernel()
{
    extern __shared__ char smc[];
    unsigned sb = (unsigned)__cvta_generic_to_shared(smc);

    const int tid = threadIdx.x;
    const int lane = tid & 31;
    const int w = tid >> 5;
    const int hb = (w & 7) << 5;          // head's fp16 col base
    const int qoff = (w >> 3) << 4;       // 0 or 16
    const int qb = blockIdx.x << 5;
    const int g = lane >> 2, tig = lane & 3;
    const int l7 = lane & 7, lb3 = (lane >> 3) & 1, lb4 = lane >> 4;

    if (tid == 0) {
        mbar_init(sb + BAR_OFF, 1);
        mbar_init(sb + BAR_OFF + 8, 1);
        mbar_init(sb + BAR_OFF + 16, 1);
        asm volatile("fence.proxy.async.shared::cta;" ::: "memory");
    }
    __syncthreads();
    if (tid == 0) {
        unsigned qbar = sb + BAR_OFF + 16;
        mbar_expect(qbar, ARR);
        bulkcp(sb + Q_OFF, (const char*)g_q16 + ((size_t)blockIdx.x << 14),
               ARR, qbar);
        stage_tile(sb, 0, 0);
        stage_tile(sb, 1, 1);
    }

    const unsigned* am = g_amask + qb + qoff + g;
    unsigned mw0 = __ldg(am);
    unsigned mw1 = __ldg(am + 8);

    mbar_wait(sb + BAR_OFF + 16, 0);

    // Q fragments (registers for whole kernel)
    unsigned qf[2][4];
#pragma unroll
    for (int kc = 0; kc < 2; kc++) {
        unsigned off = swz(qoff + (lane & 15), hb + kc * 16 + ((lane >> 4) << 3));
        uint4 r;
        ldsm4(r, sb + Q_OFF + off);
        qf[kc][0] = r.x; qf[kc][1] = r.y; qf[kc][2] = r.z; qf[kc][3] = r.w;
    }

    float oc[4][4];
#pragma unroll
    for (int i = 0; i < 4; i++)
#pragma unroll
        for (int j = 0; j < 4; j++) oc[i][j] = 0.f;
    float l0 = 0.f, l1 = 0.f;

    for (int t = 0; t < 128; t++) {
        unsigned nw0 = 0, nw1 = 0;
        if (t < 127) {
            nw0 = __ldg(am + (t + 1) * NTOK);
            nw1 = __ldg(am + (t + 1) * NTOK + 8);
        }
        const int cur = t & 1;
        mbar_wait(sb + BAR_OFF + cur * 8, (t >> 1) & 1);
        const unsigned tb = sb + TILE_OFF + cur * BUF;

        // ---- K fragments ----
        uint4 kf[2][2];
#pragma unroll
        for (int kc = 0; kc < 2; kc++)
#pragma unroll
            for (int p = 0; p < 2; p++)
                ldsm4(kf[kc][p], tb + swz(16 * p + lb4 * 8 + l7,
                                          hb + kc * 16 + lb3 * 8));

        // ---- S = q @ k^T (fp16, f32 acc) ----
        float sc[4][4];
#pragma unroll
        for (int i = 0; i < 4; i++)
#pragma unroll
            for (int j = 0; j < 4; j++) sc[i][j] = 0.f;
#pragma unroll
        for (int nt = 0; nt < 4; nt++) {
            const int p = nt >> 1, s = nt & 1;
#pragma unroll
            for (int kc = 0; kc < 2; kc++) {
                unsigned b0 = s ? kf[kc][p].z : kf[kc][p].x;
                unsigned b1 = s ? kf[kc][p].w : kf[kc][p].y;
                mma_f16(sc[nt][0], sc[nt][1], sc[nt][2], sc[nt][3],
                        qf[kc][0], qf[kc][1], qf[kc][2], qf[kc][3], b0, b1);
            }
        }

        // ---- mask + exp (fixed shift, fp16x2 MUFU) + l accumulation ----
        unsigned pA[4][2];
        __half2 lh0 = __float2half2_rn(0.f), lh1 = __float2half2_rn(0.f);
#pragma unroll
        for (int nt = 0; nt < 4; nt++) {
            int j0 = nt * 8 + 2 * tig;
            float s0 = ((mw0 >> j0) & 1) ? sc[nt][0] : NEGL2;
            float s1 = ((mw0 >> (j0 + 1)) & 1) ? sc[nt][1] : NEGL2;
            float s2 = ((mw1 >> j0) & 1) ? sc[nt][2] : NEGL2;
            float s3 = ((mw1 >> (j0 + 1)) & 1) ? sc[nt][3] : NEGL2;
            unsigned h0, h1;
            PKH(h0, s0, s1);
            PKH(h1, s2, s3);
            EX2H2(pA[nt][0], h0);
            EX2H2(pA[nt][1], h1);
            lh0 = __hadd2(lh0, *(__half2*)&pA[nt][0]);
            lh1 = __hadd2(lh1, *(__half2*)&pA[nt][1]);
        }
        {
            float2 f0 = __half22float2(lh0);
            float2 f1 = __half22float2(lh1);
            l0 += f0.x + f0.y;
            l1 += f1.x + f1.y;
        }

        // ---- V fragments (trans) ----
        uint4 vf[2][2];
#pragma unroll
        for (int kc = 0; kc < 2; kc++)
#pragma unroll
            for (int p = 0; p < 2; p++)
                ldsm4t(vf[kc][p], tb + ARR + swz(kc * 16 + lb3 * 8 + l7,
                                                 hb + p * 16 + lb4 * 8));

        // ---- O += P @ V ----
#pragma unroll
        for (int nt = 0; nt < 4; nt++) {
            const int p = nt >> 1, s = nt & 1;
#pragma unroll
            for (int kc = 0; kc < 2; kc++) {
                unsigned b0 = s ? vf[kc][p].z : vf[kc][p].x;
                unsigned b1 = s ? vf[kc][p].w : vf[kc][p].y;
                mma_f16(oc[nt][0], oc[nt][1], oc[nt][2], oc[nt][3],
                        pA[2 * kc][0], pA[2 * kc][1],
                        pA[2 * kc + 1][0], pA[2 * kc + 1][1], b0, b1);
            }
        }

        __syncthreads();
        if (tid == 0 && t < 126) stage_tile(sb, t + 2, cur);
        mw0 = nw0; mw1 = nw1;
    }

    // ---- final l reduction across the 4-thread group + epilogue ----
    l0 += __shfl_xor_sync(0xffffffffu, l0, 1);
    l0 += __shfl_xor_sync(0xffffffffu, l0, 2);
    l1 += __shfl_xor_sync(0xffffffffu, l1, 1);
    l1 += __shfl_xor_sync(0xffffffffu, l1, 2);
    float inv0 = 1.f / l0, inv1 = 1.f / l1;
    float* o0 = g_att + (size_t)(qb + qoff + g) * 256 + hb;
    float* o1 = g_att + (size_t)(qb + qoff + g + 8) * 256 + hb;
#pragma unroll
    for (int nt = 0; nt < 4; nt++) {
        float2 a = {oc[nt][0] * inv0, oc[nt][1] * inv0};
        float2 b = {oc[nt][2] * inv1, oc[nt][3] * inv1};
        *(float2*)(o0 + nt * 8 + 2 * tig) = a;
        *(float2*)(o1 + nt * 8 + 2 * tig) = b;
    }
}

// ---------------------------------------------------------------------------
extern "C" void kernel_launch(void* const* d_in, const int* in_sizes, int n_in,
                              void* d_out, int out_size)
{
    (void)in_sizes; (void)n_in; (void)out_size;
    const float* x   = (const float*)d_in[0];
    const float* adj = (const float*)d_in[1];
    const float* Wq  = (const float*)d_in[2];
    const float* bq  = (const float*)d_in[3];
    const float* Wk  = (const float*)d_in[4];
    const float* bk  = (const float*)d_in[5];
    const float* Wv  = (const float*)d_in[6];
    const float* bv  = (const float*)d_in[7];
    const float* Wo  = (const float*)d_in[8];
    const float* bo  = (const float*)d_in[9];
    float* out = (float*)d_out;

    float* pa;
    cudaGetSymbolAddress((void**)&pa, g_att);

    cudaFuncSetAttribute(attn_kernel,
                         cudaFuncAttributeMaxDynamicSharedMemorySize, SMEM_BYTES);

    dim3 gg(64, 4);
    mask_kernel<<<512, 256>>>(adj);
    gemm_qkv_kernel<<<gg, 256>>>(x, Wq, bq, Wk, bk, Wv, bv);
    attn_kernel<<<128, 512, SMEM_BYTES>>>();
    gemm_out_kernel<<<gg, 256>>>(pa, Wo, bo, out);
}

// round 7
// speedup vs baseline: 9.5640x; 1.1931x over previous
#include <cuda_runtime.h>
#include <cuda_fp16.h>
#include <cuda_bf16.h>
#include <math.h>

#define NTOK 4096
#define QSCALE 0.2550760660737454f   /* (1/sqrt(32)) * log2(e) */
#define NEGL2  -1e30f
#define PLANEB 524288                /* bytes per head-pair plane: 4096*64*2 */

// ---- device scratch (allocation-free rule) ----
// A-layout (bf16, ldmatrix-swizzled rows of 512B): xh/xl, atth/attl [4096][256]
// W-layout: transposed weights [1024 n][256 k] hi/lo (q:0-255,k:256-511,v:512-767,o:768-1023)
// QKV fp16: 4 head-pair planes, each [4096][64], 128B swizzled rows.
static __device__ __align__(1024) __nv_bfloat16 g_xh[NTOK * 256], g_xl[NTOK * 256];
static __device__ __align__(1024) __nv_bfloat16 g_ath[NTOK * 256], g_atl[NTOK * 256];
static __device__ __align__(1024) __nv_bfloat16 g_wth[1024 * 256], g_wtl[1024 * 256];
static __device__ __align__(1024) __half g_q16[NTOK * 256];
static __device__ __align__(1024) __half g_k16[NTOK * 256];
static __device__ __align__(1024) __half g_v16[NTOK * 256];
static __device__ __align__(1024) unsigned g_amask[128 * NTOK];   // [tile][q]

// ---------------- helpers ----------------
#define PKH(d, lo, hi) \
    asm("cvt.rn.f16x2.f32 %0, %1, %2;" : "=r"(d) : "f"(hi), "f"(lo))
#define PKBF(d, lo, hi) \
    asm("cvt.rn.bf16x2.f32 %0, %1, %2;" : "=r"(d) : "f"(hi), "f"(lo))
#define EX2H2(d, a) \
    asm("ex2.approx.f16x2 %0, %1;" : "=r"(d) : "r"(a))

__device__ __forceinline__ void ldsm4(uint4& r, unsigned addr) {
    asm volatile("ldmatrix.sync.aligned.m8n8.x4.shared.b16 {%0,%1,%2,%3}, [%4];"
                 : "=r"(r.x), "=r"(r.y), "=r"(r.z), "=r"(r.w) : "r"(addr));
}
__device__ __forceinline__ void ldsm4t(uint4& r, unsigned addr) {
    asm volatile("ldmatrix.sync.aligned.m8n8.x4.trans.shared.b16 {%0,%1,%2,%3}, [%4];"
                 : "=r"(r.x), "=r"(r.y), "=r"(r.z), "=r"(r.w) : "r"(addr));
}
__device__ __forceinline__ void mma_f16(
    float& d0, float& d1, float& d2, float& d3,
    unsigned a0, unsigned a1, unsigned a2, unsigned a3,
    unsigned b0, unsigned b1)
{
    asm("mma.sync.aligned.m16n8k16.row.col.f32.f16.f16.f32 "
        "{%0,%1,%2,%3},{%4,%5,%6,%7},{%8,%9},{%0,%1,%2,%3};"
        : "+f"(d0), "+f"(d1), "+f"(d2), "+f"(d3)
        : "r"(a0), "r"(a1), "r"(a2), "r"(a3), "r"(b0), "r"(b1));
}
__device__ __forceinline__ void mma_bf16(
    float& d0, float& d1, float& d2, float& d3,
    unsigned a0, unsigned a1, unsigned a2, unsigned a3,
    unsigned b0, unsigned b1)
{
    asm("mma.sync.aligned.m16n8k16.row.col.f32.bf16.bf16.f32 "
        "{%0,%1,%2,%3},{%4,%5,%6,%7},{%8,%9},{%0,%1,%2,%3};"
        : "+f"(d0), "+f"(d1), "+f"(d2), "+f"(d3)
        : "r"(a0), "r"(a1), "r"(a2), "r"(a3), "r"(b0), "r"(b1));
}
__device__ __forceinline__ void mbar_init(unsigned addr, unsigned cnt) {
    asm volatile("mbarrier.init.shared.b64 [%0], %1;" :: "r"(addr), "r"(cnt) : "memory");
}
__device__ __forceinline__ void mbar_expect(unsigned addr, unsigned tx) {
    asm volatile("mbarrier.arrive.expect_tx.shared.b64 _, [%0], %1;"
                 :: "r"(addr), "r"(tx) : "memory");
}
__device__ __forceinline__ void mbar_wait(unsigned addr, unsigned phase) {
    unsigned done = 0;
    while (!done) {
        asm volatile(
            "{\n .reg .pred p;\n"
            " mbarrier.try_wait.parity.acquire.cta.shared::cta.b64 p, [%1], %2, 0x989680;\n"
            " selp.b32 %0, 1, 0, p;\n}"
            : "=r"(done) : "r"(addr), "r"(phase) : "memory");
    }
}
__device__ __forceinline__ void bulkcp(unsigned dst, const void* src,
                                       unsigned bytes, unsigned mbar) {
    unsigned long long ga;
    asm("cvta.to.global.u64 %0, %1;" : "=l"(ga) : "l"(src));
    asm volatile(
        "cp.async.bulk.shared::cta.global.mbarrier::complete_tx::bytes "
        "[%0], [%1], %2, [%3];"
        :: "r"(dst), "l"(ga), "r"(bytes), "r"(mbar) : "memory");
}

// A/W layout: 512-byte rows; chunk-xor swizzle (xor affects low 3 chunk bits)
__device__ __forceinline__ unsigned swzA(int row, int col) {
    return (unsigned)(row * 512 + ((((col >> 3) ^ (row & 7))) << 4)
                      + ((col & 7) << 1));
}
// plane layout: 128-byte rows (64 fp16 cols)
__device__ __forceinline__ unsigned swzP(int row, int c) {
    return (unsigned)(row * 128 + ((((c >> 3) ^ (row & 7))) << 4)
                      + ((c & 7) << 1));
}

// ---------------------------------------------------------------------------
// adj -> bitmask, coalesced: one warp per query row.
// ---------------------------------------------------------------------------
__global__ __launch_bounds__(256) void mask_kernel(const float* __restrict__ adj)
{
    const int q = (blockIdx.x << 3) + (threadIdx.x >> 5);
    const int lane = threadIdx.x & 31;
    const float* row = adj + (size_t)q * NTOK + lane;
#pragma unroll 4
    for (int t = 0; t < 128; t++) {
        float v = row[t << 5];
        unsigned w = __ballot_sync(0xffffffffu, v > 0.f);
        if (lane == 0) g_amask[t * NTOK + q] = w;
    }
}

// ---------------------------------------------------------------------------
// prep_x: x fp32 -> hi/lo bf16, A-layout swizzled.
// ---------------------------------------------------------------------------
__global__ __launch_bounds__(256) void prep_x_kernel(const float* __restrict__ x)
{
    int idx = blockIdx.x * 256 + threadIdx.x;        // 0..262143
    int row = idx >> 6;
    int c4 = (idx & 63) << 2;
    float4 v = *(const float4*)&x[row * 256 + c4];
    unsigned h0, h1, l0, l1;
    PKBF(h0, v.x, v.y);
    PKBF(h1, v.z, v.w);
    float r0 = v.x - __uint_as_float(h0 << 16);
    float r1 = v.y - __uint_as_float(h0 & 0xffff0000u);
    float r2 = v.z - __uint_as_float(h1 << 16);
    float r3 = v.w - __uint_as_float(h1 & 0xffff0000u);
    PKBF(l0, r0, r1);
    PKBF(l1, r2, r3);
    unsigned off = swzA(row, c4);
    uint2 hw = {h0, h1}, lw = {l0, l1};
    *(uint2*)((char*)g_xh + off) = hw;
    *(uint2*)((char*)g_xl + off) = lw;
}

// ---------------------------------------------------------------------------
// prep_w: W[k][n] (4 matrices) -> Wt[n][k] hi/lo bf16, A-layout swizzled.
// grid (8 kblocks, 32 nblocks), block (32, 8).
// ---------------------------------------------------------------------------
__global__ void prep_w_kernel(const float* __restrict__ Wq,
                              const float* __restrict__ Wk,
                              const float* __restrict__ Wv,
                              const float* __restrict__ Wo)
{
    __shared__ float sm[32][33];
    const int tx = threadIdx.x, ty = threadIdx.y;
    const int kb = blockIdx.x * 32;
    const int nbi = blockIdx.y;
    const int plane = nbi >> 3;
    const float* W = plane == 0 ? Wq : plane == 1 ? Wk : plane == 2 ? Wv : Wo;
    const int nloc = (nbi & 7) * 32;
#pragma unroll
    for (int i = 0; i < 4; i++) {
        int kr = ty * 4 + i;
        sm[kr][tx] = W[(kb + kr) * 256 + nloc + tx];
    }
    __syncthreads();
#pragma unroll
    for (int i = 0; i < 4; i++) {
        int nr = ty * 4 + i;                 // local n row
        float v = sm[tx][nr];                // W[kb+tx][nloc+nr]
        __nv_bfloat16 h = __float2bfloat16_rn(v);
        __nv_bfloat16 l = __float2bfloat16_rn(v - __bfloat162float(h));
        int grow = plane * 256 + nloc + nr;
        unsigned off = swzA(grow, kb + tx);
        *(__nv_bfloat16*)((char*)g_wth + off) = h;
        *(__nv_bfloat16*)((char*)g_wtl + off) = l;
    }
}

// ---------------------------------------------------------------------------
// Tensor-core GEMM: C[m][n] = A[m][k=256] @ Wt[n][k]^T (+bias).
// Block 256 thr / 8 warps, tile M=64 N=64, warp 16x32, full K resident.
// 3-term bf16 split (Ah*Wh + Al*Wh + Ah*Wl) ~= fp32.
// MODE 0: A = x, n in 0..767 -> fp16 q/k/v planes (+bias, q*QSCALE).
// MODE 1: A = att, W rows 768.. -> fp32 out + bo.
// ---------------------------------------------------------------------------
#define GA_H 0
#define GA_L 32768
#define GW_H 65536
#define GW_L 98304
#define GBAR 131072
#define GSMEM 131104

template <int MODE>
__global__ __launch_bounds__(256, 1) void gemm_tc_kernel(
    const float* __restrict__ bias0, const float* __restrict__ bias1,
    const float* __restrict__ bias2, float* __restrict__ C)
{
    extern __shared__ char smc[];
    unsigned sb = (unsigned)__cvta_generic_to_shared(smc);

    const int tid = threadIdx.x;
    const int lane = tid & 31;
    const int w = tid >> 5;
    const int wm = (w & 3) << 4;          // warp m base (0..48)
    const int wn = (w >> 2) << 5;         // warp n base (0 or 32)
    const int mb = blockIdx.x * 64;
    const int nb = blockIdx.y * 64;
    const int g = lane >> 2, tig = lane & 3;
    const int l7 = lane & 7, lb3 = (lane >> 3) & 1, lb4 = lane >> 4;

    if (tid == 0) {
        mbar_init(sb + GBAR, 1);
        asm volatile("fence.proxy.async.shared::cta;" ::: "memory");
        mbar_expect(sb + GBAR, 131072);
        const char* ah = MODE == 0 ? (const char*)g_xh : (const char*)g_ath;
        const char* al = MODE == 0 ? (const char*)g_xl : (const char*)g_atl;
        int wrow = (MODE == 0 ? 0 : 768) + nb;
        bulkcp(sb + GA_H, ah + (size_t)mb * 512, 32768, sb + GBAR);
        bulkcp(sb + GA_L, al + (size_t)mb * 512, 32768, sb + GBAR);
        bulkcp(sb + GW_H, (const char*)g_wth + (size_t)wrow * 512, 32768, sb + GBAR);
        bulkcp(sb + GW_L, (const char*)g_wtl + (size_t)wrow * 512, 32768, sb + GBAR);
    }
    __syncthreads();
    mbar_wait(sb + GBAR, 0);

    float acc[4][4];
#pragma unroll
    for (int i = 0; i < 4; i++)
#pragma unroll
        for (int j = 0; j < 4; j++) acc[i][j] = 0.f;

#pragma unroll
    for (int kc = 0; kc < 16; kc++) {
        uint4 ah, al;
        {
            unsigned off = swzA(wm + (lane & 15), kc * 16 + ((lane >> 4) << 3));
            ldsm4(ah, sb + GA_H + off);
            ldsm4(al, sb + GA_L + off);
        }
        uint4 wh[2], wl[2];
#pragma unroll
        for (int p = 0; p < 2; p++) {
            unsigned off = swzA(wn + 16 * p + lb4 * 8 + l7, kc * 16 + lb3 * 8);
            ldsm4(wh[p], sb + GW_H + off);
            ldsm4(wl[p], sb + GW_L + off);
        }
#pragma unroll
        for (int nf = 0; nf < 4; nf++) {
            const int p = nf >> 1, s = nf & 1;
            unsigned bh0 = s ? wh[p].z : wh[p].x;
            unsigned bh1 = s ? wh[p].w : wh[p].y;
            unsigned bl0 = s ? wl[p].z : wl[p].x;
            unsigned bl1 = s ? wl[p].w : wl[p].y;
            mma_bf16(acc[nf][0], acc[nf][1], acc[nf][2], acc[nf][3],
                     ah.x, ah.y, ah.z, ah.w, bh0, bh1);
            mma_bf16(acc[nf][0], acc[nf][1], acc[nf][2], acc[nf][3],
                     al.x, al.y, al.z, al.w, bh0, bh1);
            mma_bf16(acc[nf][0], acc[nf][1], acc[nf][2], acc[nf][3],
                     ah.x, ah.y, ah.z, ah.w, bl0, bl1);
        }
    }

    const int r0 = mb + wm + g;
    if (MODE == 0) {
        const int plane = nb >> 8;
        const float* bias = plane == 0 ? bias0 : plane == 1 ? bias1 : bias2;
        __half* dst = plane == 0 ? g_q16 : plane == 1 ? g_k16 : g_v16;
        const float scale = plane == 0 ? QSCALE : 1.0f;
        const int colb = (nb & 255) + wn + tig * 2;
#pragma unroll
        for (int nf = 0; nf < 4; nf++) {
            int c = colb + nf * 8;
            float b0 = bias[c], b1 = bias[c + 1];
            float v00 = (acc[nf][0] + b0) * scale;
            float v01 = (acc[nf][1] + b1) * scale;
            float v10 = (acc[nf][2] + b0) * scale;
            float v11 = (acc[nf][3] + b1) * scale;
            unsigned p0, p1;
            PKH(p0, v00, v01);
            PKH(p1, v10, v11);
            size_t pb = (size_t)(c >> 6) * PLANEB;
            *(unsigned*)((char*)dst + pb + swzP(r0, c & 63)) = p0;
            *(unsigned*)((char*)dst + pb + swzP(r0 + 8, c & 63)) = p1;
        }
    } else {
        const int colb = nb + wn + tig * 2;
#pragma unroll
        for (int nf = 0; nf < 4; nf++) {
            int c = colb + nf * 8;
            float b0 = bias0[c], b1 = bias0[c + 1];
            float2 o0 = {acc[nf][0] + b0, acc[nf][1] + b1};
            float2 o1 = {acc[nf][2] + b0, acc[nf][3] + b1};
            *(float2*)&C[(size_t)r0 * 256 + c] = o0;
            *(float2*)&C[(size_t)(r0 + 8) * 256 + c] = o1;
        }
    }
}

// ---------------------------------------------------------------------------
// fp16 flash attention on head-pair planes (4x less L2 traffic).
// grid 128 = 32 q-tiles x 4 planes; block 512 thr / 16 warps:
// warp w -> q-slice w>>1 (16 rows of the 128-query tile), head w&1.
// ---------------------------------------------------------------------------
#define AQ_OFF 0
#define AT_OFF 16384
#define ABUF 8192
#define ABAR 49152
#define ASMEM 49184

__device__ __forceinline__ void stage_kv(unsigned sb, int t, int buf,
                                         size_t plane_off) {
    unsigned bar = sb + ABAR + buf * 8;
    unsigned base = sb + AT_OFF + buf * ABUF;
    size_t go = plane_off + (size_t)t * 4096;
    mbar_expect(bar, 8192);
    bulkcp(base,        (const char*)g_k16 + go, 4096, bar);
    bulkcp(base + 4096, (const char*)g_v16 + go, 4096, bar);
}

__global__ __launch_bounds__(512, 1) void attn_kernel()
{
    extern __shared__ char smc[];
    unsigned sb = (unsigned)__cvta_generic_to_shared(smc);

    const int tid = threadIdx.x;
    const int lane = tid & 31;
    const int w = tid >> 5;
    const int hw = w & 1;                 // head within pair
    const int qs = (w >> 1) << 4;         // q-slice base (0..112)
    const int hcb = hw << 5;              // col base in plane
    const int qtile = blockIdx.x & 31;
    const int hp = blockIdx.x >> 5;
    const int qb = qtile << 7;            // 128 queries per block
    const size_t plane_off = (size_t)hp * PLANEB;
    const int g = lane >> 2, tig = lane & 3;
    const int l7 = lane & 7, lb3 = (lane >> 3) & 1, lb4 = lane >> 4;

    if (tid == 0) {
        mbar_init(sb + ABAR, 1);
        mbar_init(sb + ABAR + 8, 1);
        mbar_init(sb + ABAR + 16, 1);
        asm volatile("fence.proxy.async.shared::cta;" ::: "memory");
    }
    __syncthreads();
    if (tid == 0) {
        unsigned qbar = sb + ABAR + 16;
        mbar_expect(qbar, 16384);
        bulkcp(sb + AQ_OFF, (const char*)g_q16 + plane_off + (size_t)qb * 128,
               16384, qbar);
        stage_kv(sb, 0, 0, plane_off);
        stage_kv(sb, 1, 1, plane_off);
    }

    const unsigned* am = g_amask + qb + qs + g;
    unsigned mw0 = __ldg(am);
    unsigned mw1 = __ldg(am + 8);

    mbar_wait(sb + ABAR + 16, 0);

    unsigned qf[2][4];
#pragma unroll
    for (int kc = 0; kc < 2; kc++) {
        unsigned off = swzP(qs + (lane & 15), hcb + kc * 16 + ((lane >> 4) << 3));
        uint4 r;
        ldsm4(r, sb + AQ_OFF + off);
        qf[kc][0] = r.x; qf[kc][1] = r.y; qf[kc][2] = r.z; qf[kc][3] = r.w;
    }

    float oc[4][4];
#pragma unroll
    for (int i = 0; i < 4; i++)
#pragma unroll
        for (int j = 0; j < 4; j++) oc[i][j] = 0.f;
    float l0 = 0.f, l1 = 0.f;

    for (int t = 0; t < 128; t++) {
        unsigned nw0 = 0, nw1 = 0;
        if (t < 127) {
            nw0 = __ldg(am + (t + 1) * NTOK);
            nw1 = __ldg(am + (t + 1) * NTOK + 8);
        }
        const int cur = t & 1;
        mbar_wait(sb + ABAR + cur * 8, (t >> 1) & 1);
        const unsigned tb = sb + AT_OFF + cur * ABUF;

        uint4 kf[2][2];
#pragma unroll
        for (int kc = 0; kc < 2; kc++)
#pragma unroll
            for (int p = 0; p < 2; p++)
                ldsm4(kf[kc][p], tb + swzP(16 * p + lb4 * 8 + l7,
                                           hcb + kc * 16 + lb3 * 8));

        float sc[4][4];
#pragma unroll
        for (int i = 0; i < 4; i++)
#pragma unroll
            for (int j = 0; j < 4; j++) sc[i][j] = 0.f;
#pragma unroll
        for (int nt = 0; nt < 4; nt++) {
            const int p = nt >> 1, s = nt & 1;
#pragma unroll
            for (int kc = 0; kc < 2; kc++) {
                unsigned b0 = s ? kf[kc][p].z : kf[kc][p].x;
                unsigned b1 = s ? kf[kc][p].w : kf[kc][p].y;
                mma_f16(sc[nt][0], sc[nt][1], sc[nt][2], sc[nt][3],
                        qf[kc][0], qf[kc][1], qf[kc][2], qf[kc][3], b0, b1);
            }
        }

        unsigned pA[4][2];
        __half2 lh0 = __float2half2_rn(0.f), lh1 = __float2half2_rn(0.f);
#pragma unroll
        for (int nt = 0; nt < 4; nt++) {
            int j0 = nt * 8 + 2 * tig;
            float s0 = ((mw0 >> j0) & 1) ? sc[nt][0] : NEGL2;
            float s1 = ((mw0 >> (j0 + 1)) & 1) ? sc[nt][1] : NEGL2;
            float s2 = ((mw1 >> j0) & 1) ? sc[nt][2] : NEGL2;
            float s3 = ((mw1 >> (j0 + 1)) & 1) ? sc[nt][3] : NEGL2;
            unsigned h0, h1;
            PKH(h0, s0, s1);
            PKH(h1, s2, s3);
            EX2H2(pA[nt][0], h0);
            EX2H2(pA[nt][1], h1);
            lh0 = __hadd2(lh0, *(__half2*)&pA[nt][0]);
            lh1 = __hadd2(lh1, *(__half2*)&pA[nt][1]);
        }
        {
            float2 f0 = __half22float2(lh0);
            float2 f1 = __half22float2(lh1);
            l0 += f0.x + f0.y;
            l1 += f1.x + f1.y;
        }

        uint4 vf[2][2];
#pragma unroll
        for (int kc = 0; kc < 2; kc++)
#pragma unroll
            for (int p = 0; p < 2; p++)
                ldsm4t(vf[kc][p], tb + 4096 + swzP(kc * 16 + lb3 * 8 + l7,
                                                   hcb + p * 16 + lb4 * 8));

#pragma unroll
        for (int nt = 0; nt < 4; nt++) {
            const int p = nt >> 1, s = nt & 1;
#pragma unroll
            for (int kc = 0; kc < 2; kc++) {
                unsigned b0 = s ? vf[kc][p].z : vf[kc][p].x;
                unsigned b1 = s ? vf[kc][p].w : vf[kc][p].y;
                mma_f16(oc[nt][0], oc[nt][1], oc[nt][2], oc[nt][3],
                        pA[2 * kc][0], pA[2 * kc][1],
                        pA[2 * kc + 1][0], pA[2 * kc + 1][1], b0, b1);
            }
        }

        __syncthreads();
        if (tid == 0 && t < 126) stage_kv(sb, t + 2, cur, plane_off);
        mw0 = nw0; mw1 = nw1;
    }

    l0 += __shfl_xor_sync(0xffffffffu, l0, 1);
    l0 += __shfl_xor_sync(0xffffffffu, l0, 2);
    l1 += __shfl_xor_sync(0xffffffffu, l1, 1);
    l1 += __shfl_xor_sync(0xffffffffu, l1, 2);
    float inv0 = 1.f / l0, inv1 = 1.f / l1;

    // epilogue -> hi/lo bf16 in A-layout for the output gemm
    const int r0 = qb + qs + g;
    const int colb = ((hp << 1) + hw) * 32 + tig * 2;
#pragma unroll
    for (int nt = 0; nt < 4; nt++) {
        int c = colb + nt * 8;
        float v00 = oc[nt][0] * inv0, v01 = oc[nt][1] * inv0;
        float v10 = oc[nt][2] * inv1, v11 = oc[nt][3] * inv1;
        unsigned h0, h1, lo0, lo1;
        PKBF(h0, v00, v01);
        PKBF(h1, v10, v11);
        float e0 = v00 - __uint_as_float(h0 << 16);
        float e1 = v01 - __uint_as_float(h0 & 0xffff0000u);
        float e2 = v10 - __uint_as_float(h1 << 16);
        float e3 = v11 - __uint_as_float(h1 & 0xffff0000u);
        PKBF(lo0, e0, e1);
        PKBF(lo1, e2, e3);
        unsigned o0 = swzA(r0, c), o1 = swzA(r0 + 8, c);
        *(unsigned*)((char*)g_ath + o0) = h0;
        *(unsigned*)((char*)g_ath + o1) = h1;
        *(unsigned*)((char*)g_atl + o0) = lo0;
        *(unsigned*)((char*)g_atl + o1) = lo1;
    }
}

// ---------------------------------------------------------------------------
extern "C" void kernel_launch(void* const* d_in, const int* in_sizes, int n_in,
                              void* d_out, int out_size)
{
    (void)in_sizes; (void)n_in; (void)out_size;
    const float* x   = (const float*)d_in[0];
    const float* adj = (const float*)d_in[1];
    const float* Wq  = (const float*)d_in[2];
    const float* bq  = (const float*)d_in[3];
    const float* Wk  = (const float*)d_in[4];
    const float* bk  = (const float*)d_in[5];
    const float* Wv  = (const float*)d_in[6];
    const float* bv  = (const float*)d_in[7];
    const float* Wo  = (const float*)d_in[8];
    const float* bo  = (const float*)d_in[9];
    float* out = (float*)d_out;

    cudaFuncSetAttribute(gemm_tc_kernel<0>,
                         cudaFuncAttributeMaxDynamicSharedMemorySize, GSMEM);
    cudaFuncSetAttribute(gemm_tc_kernel<1>,
                         cudaFuncAttributeMaxDynamicSharedMemorySize, GSMEM);
    cudaFuncSetAttribute(attn_kernel,
                         cudaFuncAttributeMaxDynamicSharedMemorySize, ASMEM);

    prep_x_kernel<<<1024, 256>>>(x);
    prep_w_kernel<<<dim3(8, 32), dim3(32, 8)>>>(Wq, Wk, Wv, Wo);
    mask_kernel<<<512, 256>>>(adj);
    gemm_tc_kernel<0><<<dim3(64, 12), 256, GSMEM>>>(bq, bk, bv, nullptr);
    attn_kernel<<<128, 512, ASMEM>>>();
    gemm_tc_kernel<1><<<dim3(64, 4), 256, GSMEM>>>(bo, nullptr, nullptr, out);
}